// round 1
// baseline (speedup 1.0000x reference)
#include <cuda_runtime.h>
#include <math.h>

// Problem constants
#define Bb   4
#define Tt   2048
#define Ee   512
#define Dd   512
#define Nn   16
#define Ll   4
#define NFf  2048
#define TC   32              // chunk length for parallel scan
#define NCH  (Tt / TC)       // 64 chunks
#define DN   (Dd * Nn)       // 8192
#define BDN  (Bb * Dd * Nn)  // 32768

// Scratch (static device globals; no runtime allocation)
__device__ float g_h[(size_t)Bb * Tt * Dd];        // residual stream, 16 MB
__device__ float g_Abar [Ll * DN];
__device__ float g_BbarB[Ll * DN];
__device__ float g_AbarP[Ll * DN];                 // Abar^TC
__device__ float g_xfin  [(size_t)NCH * BDN];      // 8 MB
__device__ float g_xstart[(size_t)NCH * BDN];      // 8 MB

// ---------------------------------------------------------------------------
// Precompute per-layer SSM constants
// ---------------------------------------------------------------------------
__global__ void precompute_kernel(const float* __restrict__ A_log,
                                  const float* __restrict__ B_ssm,
                                  const float* __restrict__ log_dt) {
    int idx = blockIdx.x * blockDim.x + threadIdx.x;
    if (idx >= Ll * DN) return;
    int l  = idx / DN;
    int dn = idx % DN;
    int d  = dn / Nn;
    float dt = expf(log_dt[l * Dd + d]);
    float A  = -expf(A_log[idx]);
    float dA = dt * A;
    float ab = expf(dA);
    g_Abar [idx] = ab;
    g_BbarB[idx] = (ab - 1.0f) / A * B_ssm[idx];
    g_AbarP[idx] = expf(dA * (float)TC);
}

// ---------------------------------------------------------------------------
// Input GEMM: h[row, col] = sum_e X[row,e]*W[e,col] + b_in[col] + freq[t,col]
// M=8192 (row = b*T + t), K=512, N=512.  BM=128, BN=64, BK=16, TM=8, TN=4.
// ---------------------------------------------------------------------------
__global__ __launch_bounds__(256)
void gemm_in_kernel(const float* __restrict__ X, const float* __restrict__ W,
                    const float* __restrict__ bias, const float* __restrict__ freq) {
    __shared__ float As[16][128];
    __shared__ float Bs[16][64];

    int tid = threadIdx.x;
    int tx = tid & 15;          // 0..15 -> N
    int ty = tid >> 4;          // 0..15 -> M
    int rowBase = blockIdx.y * 128;
    int colBase = blockIdx.x * 64;

    float acc[8][4];
#pragma unroll
    for (int i = 0; i < 8; i++)
#pragma unroll
        for (int j = 0; j < 4; j++) acc[i][j] = 0.0f;

    int aRow = tid >> 2;            // 0..63
    int aCol = (tid & 3) << 2;      // 0,4,8,12
    int bRow = tid >> 4;            // 0..15
    int bCol = (tid & 15) << 2;     // 0..60

    const float* Xp = X + (size_t)rowBase * Ee;

    for (int kt = 0; kt < Ee; kt += 16) {
        float4 a0 = *(const float4*)(Xp + (size_t)aRow        * Ee + kt + aCol);
        float4 a1 = *(const float4*)(Xp + (size_t)(aRow + 64) * Ee + kt + aCol);
        As[aCol + 0][aRow]      = a0.x;
        As[aCol + 1][aRow]      = a0.y;
        As[aCol + 2][aRow]      = a0.z;
        As[aCol + 3][aRow]      = a0.w;
        As[aCol + 0][aRow + 64] = a1.x;
        As[aCol + 1][aRow + 64] = a1.y;
        As[aCol + 2][aRow + 64] = a1.z;
        As[aCol + 3][aRow + 64] = a1.w;
        float4 bv = *(const float4*)(W + (size_t)(kt + bRow) * Dd + colBase + bCol);
        *(float4*)&Bs[bRow][bCol] = bv;
        __syncthreads();

#pragma unroll
        for (int k = 0; k < 16; k++) {
            float ar[8], br[4];
            *(float4*)(ar)     = *(const float4*)&As[k][ty * 8];
            *(float4*)(ar + 4) = *(const float4*)&As[k][ty * 8 + 4];
            *(float4*)(br)     = *(const float4*)&Bs[k][tx * 4];
#pragma unroll
            for (int i = 0; i < 8; i++)
#pragma unroll
                for (int j = 0; j < 4; j++)
                    acc[i][j] = fmaf(ar[i], br[j], acc[i][j]);
        }
        __syncthreads();
    }

#pragma unroll
    for (int i = 0; i < 8; i++) {
        int row = rowBase + ty * 8 + i;
        int t   = row & (Tt - 1);           // row = b*T + t, T pow2
        const float* fr = freq + (size_t)t * Dd;
#pragma unroll
        for (int j = 0; j < 4; j++) {
            int col = colBase + tx * 4 + j;
            g_h[(size_t)row * Dd + col] = acc[i][j] + bias[col] + fr[col];
        }
    }
}

// ---------------------------------------------------------------------------
// Scan phase 1: per-chunk scan from zero state -> chunk-final states
// grid = B*NCH blocks, block = D threads (thread d handles channel (b,d,c))
// ---------------------------------------------------------------------------
__global__ __launch_bounds__(512)
void scan1_kernel(int l) {
    int d = threadIdx.x;
    int b = blockIdx.x / NCH;
    int c = blockIdx.x % NCH;

    float ab[16], bb[16];
    const float4* abp = (const float4*)(g_Abar  + (size_t)l * DN + d * Nn);
    const float4* bbp = (const float4*)(g_BbarB + (size_t)l * DN + d * Nn);
#pragma unroll
    for (int q = 0; q < 4; q++) {
        float4 va = abp[q]; float4 vb = bbp[q];
        ab[4*q+0]=va.x; ab[4*q+1]=va.y; ab[4*q+2]=va.z; ab[4*q+3]=va.w;
        bb[4*q+0]=vb.x; bb[4*q+1]=vb.y; bb[4*q+2]=vb.z; bb[4*q+3]=vb.w;
    }

    float x[16];
#pragma unroll
    for (int n = 0; n < 16; n++) x[n] = 0.0f;

    const float* up = g_h + ((size_t)b * Tt + (size_t)c * TC) * Dd + d;
#pragma unroll 4
    for (int i = 0; i < TC; i++) {
        float u = up[(size_t)i * Dd];
#pragma unroll
        for (int n = 0; n < 16; n++)
            x[n] = fmaf(ab[n], x[n], bb[n] * u);
    }

    float4* xo = (float4*)(g_xfin + (size_t)c * BDN + ((size_t)b * Dd + d) * Nn);
#pragma unroll
    for (int q = 0; q < 4; q++)
        xo[q] = make_float4(x[4*q+0], x[4*q+1], x[4*q+2], x[4*q+3]);
}

// ---------------------------------------------------------------------------
// Scan phase 2: sequential recurrence across chunks (per (b,d,n))
// x_start[c] = Abar^TC * x_start[c-1] + x_final[c-1]
// ---------------------------------------------------------------------------
__global__ __launch_bounds__(256)
void scan2_kernel(int l) {
    int idx = blockIdx.x * blockDim.x + threadIdx.x;   // (b*D+d)*N + n
    if (idx >= BDN) return;
    float ap = g_AbarP[(size_t)l * DN + (idx % DN)];
    float x = 0.0f;
    for (int c = 0; c < NCH; c++) {
        g_xstart[(size_t)c * BDN + idx] = x;
        x = fmaf(ap, x, g_xfin[(size_t)c * BDN + idx]);
    }
}

// ---------------------------------------------------------------------------
// Scan phase 3: re-scan with correct start state; fused y = C.x, D_skip,
// tanh-GELU, residual; h updated in place.
// ---------------------------------------------------------------------------
__global__ __launch_bounds__(512)
void scan3_kernel(int l, const float* __restrict__ C_ssm,
                  const float* __restrict__ D_skip) {
    int d = threadIdx.x;
    int b = blockIdx.x / NCH;
    int c = blockIdx.x % NCH;

    float ab[16], bb[16], cc[16];
    const float4* abp = (const float4*)(g_Abar  + (size_t)l * DN + d * Nn);
    const float4* bbp = (const float4*)(g_BbarB + (size_t)l * DN + d * Nn);
    const float4* ccp = (const float4*)(C_ssm   + (size_t)l * DN + d * Nn);
#pragma unroll
    for (int q = 0; q < 4; q++) {
        float4 va = abp[q]; float4 vb = bbp[q]; float4 vc = ccp[q];
        ab[4*q+0]=va.x; ab[4*q+1]=va.y; ab[4*q+2]=va.z; ab[4*q+3]=va.w;
        bb[4*q+0]=vb.x; bb[4*q+1]=vb.y; bb[4*q+2]=vb.z; bb[4*q+3]=vb.w;
        cc[4*q+0]=vc.x; cc[4*q+1]=vc.y; cc[4*q+2]=vc.z; cc[4*q+3]=vc.w;
    }
    float dsk = D_skip[l * Dd + d];

    float x[16];
    const float4* xs = (const float4*)(g_xstart + (size_t)c * BDN + ((size_t)b * Dd + d) * Nn);
#pragma unroll
    for (int q = 0; q < 4; q++) {
        float4 v = xs[q];
        x[4*q+0]=v.x; x[4*q+1]=v.y; x[4*q+2]=v.z; x[4*q+3]=v.w;
    }

    float* hp = g_h + ((size_t)b * Tt + (size_t)c * TC) * Dd + d;
#pragma unroll 2
    for (int i = 0; i < TC; i++) {
        float u = hp[(size_t)i * Dd];
        float y = 0.0f;
#pragma unroll
        for (int n = 0; n < 16; n++) {
            x[n] = fmaf(ab[n], x[n], bb[n] * u);
            y = fmaf(x[n], cc[n], y);
        }
        y = fmaf(dsk, u, y);
        // JAX default gelu (tanh approximation)
        float y3 = y * y * y;
        float inner = 0.7978845608028654f * (y + 0.044715f * y3);
        float g = 0.5f * y * (1.0f + tanhf(inner));
        hp[(size_t)i * Dd] = u + g;
    }
}

// ---------------------------------------------------------------------------
// Head: dual LayerNorm + two scalar projections. One block per (b,t) row.
// ---------------------------------------------------------------------------
__device__ __forceinline__ float blockReduce256(float v, float* sh) {
#pragma unroll
    for (int o = 16; o > 0; o >>= 1) v += __shfl_xor_sync(0xffffffffu, v, o);
    int lane = threadIdx.x & 31, w = threadIdx.x >> 5;
    if (lane == 0) sh[w] = v;
    __syncthreads();
    if (w == 0) {
        v = (lane < 8) ? sh[lane] : 0.0f;
#pragma unroll
        for (int o = 4; o > 0; o >>= 1) v += __shfl_xor_sync(0xffffffffu, v, o);
        if (lane == 0) sh[0] = v;
    }
    __syncthreads();
    float r = sh[0];
    __syncthreads();
    return r;
}

__global__ __launch_bounds__(256)
void head_kernel(const float* __restrict__ s_f0, const float* __restrict__ bi_f0,
                 const float* __restrict__ w_f0, const float* __restrict__ b_f0,
                 const float* __restrict__ s_en, const float* __restrict__ bi_en,
                 const float* __restrict__ w_en, const float* __restrict__ b_en,
                 float* __restrict__ out) {
    __shared__ float sh[32];
    int row = blockIdx.x;
    const float* hp = g_h + (size_t)row * Dd;
    int t0 = threadIdx.x, t1 = threadIdx.x + 256;
    float v0 = hp[t0], v1 = hp[t1];

    float s  = blockReduce256(v0 + v1, sh);
    float ss = blockReduce256(v0 * v0 + v1 * v1, sh);
    float mu   = s * (1.0f / Dd);
    float var  = ss * (1.0f / Dd) - mu * mu;
    float rstd = rsqrtf(var + 1e-5f);

    float n0 = (v0 - mu) * rstd, n1 = (v1 - mu) * rstd;
    float f0c = fmaf(n0, s_f0[t0], bi_f0[t0]) * w_f0[t0]
              + fmaf(n1, s_f0[t1], bi_f0[t1]) * w_f0[t1];
    float enc = fmaf(n0, s_en[t0], bi_en[t0]) * w_en[t0]
              + fmaf(n1, s_en[t1], bi_en[t1]) * w_en[t1];

    f0c = blockReduce256(f0c, sh);
    enc = blockReduce256(enc, sh);
    if (threadIdx.x == 0) {
        out[row]                     = f0c + b_f0[0];
        out[(size_t)Bb * Tt + row]   = enc + b_en[0];
    }
}

// ---------------------------------------------------------------------------
extern "C" void kernel_launch(void* const* d_in, const int* in_sizes, int n_in,
                              void* d_out, int out_size) {
    const float* text_emb = (const float*)d_in[0];
    const float* W_in     = (const float*)d_in[1];
    const float* b_in     = (const float*)d_in[2];
    const float* freq_pe  = (const float*)d_in[3];
    const float* A_log    = (const float*)d_in[4];
    const float* B_ssm    = (const float*)d_in[5];
    const float* C_ssm    = (const float*)d_in[6];
    const float* log_dt   = (const float*)d_in[7];
    const float* D_skip   = (const float*)d_in[8];
    const float* ln_f0_s  = (const float*)d_in[9];
    const float* ln_f0_b  = (const float*)d_in[10];
    const float* W_f0     = (const float*)d_in[11];
    const float* b_f0     = (const float*)d_in[12];
    const float* ln_en_s  = (const float*)d_in[13];
    const float* ln_en_b  = (const float*)d_in[14];
    const float* W_en     = (const float*)d_in[15];
    const float* b_en     = (const float*)d_in[16];
    float* out = (float*)d_out;

    precompute_kernel<<<(Ll * DN + 255) / 256, 256>>>(A_log, B_ssm, log_dt);

    dim3 ggrid(Dd / 64, (Bb * Tt) / 128);
    gemm_in_kernel<<<ggrid, 256>>>(text_emb, W_in, b_in, freq_pe);

    for (int l = 0; l < Ll; l++) {
        scan1_kernel<<<Bb * NCH, Dd>>>(l);
        scan2_kernel<<<BDN / 256, 256>>>(l);
        scan3_kernel<<<Bb * NCH, Dd>>>(l, C_ssm, D_skip);
    }

    head_kernel<<<Bb * Tt, 256>>>(ln_f0_s, ln_f0_b, W_f0, b_f0,
                                  ln_en_s, ln_en_b, W_en, b_en, out);
}

// round 2
// speedup vs baseline: 1.2461x; 1.2461x over previous
#include <cuda_runtime.h>
#include <math.h>

// Problem constants
#define Bb   4
#define Tt   2048
#define Ee   512
#define Dd   512
#define Nn   16
#define Ll   4
#define TC   32              // chunk length for parallel scan
#define NCH  (Tt / TC)       // 64 chunks
#define DN   (Dd * Nn)       // 8192
#define DBLK 8               // d-channels per block in fused scan

// Scratch (static device globals; no runtime allocation)
__device__ float g_h[(size_t)Bb * Tt * Dd];        // residual stream, 16 MB
__device__ float g_Abar [Ll * DN];
__device__ float g_BbarB[Ll * DN];
__device__ float g_AbarP[Ll * DN];                 // Abar^TC

// ---------------------------------------------------------------------------
// Precompute per-layer SSM constants
// ---------------------------------------------------------------------------
__global__ void precompute_kernel(const float* __restrict__ A_log,
                                  const float* __restrict__ B_ssm,
                                  const float* __restrict__ log_dt) {
    int idx = blockIdx.x * blockDim.x + threadIdx.x;
    if (idx >= Ll * DN) return;
    int l  = idx / DN;
    int dn = idx % DN;
    int d  = dn / Nn;
    float dt = expf(log_dt[l * Dd + d]);
    float A  = -expf(A_log[idx]);
    float dA = dt * A;
    float ab = expf(dA);
    g_Abar [idx] = ab;
    g_BbarB[idx] = (ab - 1.0f) / A * B_ssm[idx];
    g_AbarP[idx] = expf(dA * (float)TC);
}

// ---------------------------------------------------------------------------
// Input GEMM: h[row, col] = sum_e X[row,e]*W[e,col] + b_in[col] + freq[t,col]
// M=8192 (row = b*T + t), K=512, N=512.  BM=128, BN=64, BK=16, TM=8, TN=4.
// ---------------------------------------------------------------------------
__global__ __launch_bounds__(256)
void gemm_in_kernel(const float* __restrict__ X, const float* __restrict__ W,
                    const float* __restrict__ bias, const float* __restrict__ freq) {
    __shared__ float As[16][128];
    __shared__ float Bs[16][64];

    int tid = threadIdx.x;
    int tx = tid & 15;          // 0..15 -> N
    int ty = tid >> 4;          // 0..15 -> M
    int rowBase = blockIdx.y * 128;
    int colBase = blockIdx.x * 64;

    float acc[8][4];
#pragma unroll
    for (int i = 0; i < 8; i++)
#pragma unroll
        for (int j = 0; j < 4; j++) acc[i][j] = 0.0f;

    int aRow = tid >> 2;            // 0..63
    int aCol = (tid & 3) << 2;      // 0,4,8,12
    int bRow = tid >> 4;            // 0..15
    int bCol = (tid & 15) << 2;     // 0..60

    const float* Xp = X + (size_t)rowBase * Ee;

    for (int kt = 0; kt < Ee; kt += 16) {
        float4 a0 = *(const float4*)(Xp + (size_t)aRow        * Ee + kt + aCol);
        float4 a1 = *(const float4*)(Xp + (size_t)(aRow + 64) * Ee + kt + aCol);
        As[aCol + 0][aRow]      = a0.x;
        As[aCol + 1][aRow]      = a0.y;
        As[aCol + 2][aRow]      = a0.z;
        As[aCol + 3][aRow]      = a0.w;
        As[aCol + 0][aRow + 64] = a1.x;
        As[aCol + 1][aRow + 64] = a1.y;
        As[aCol + 2][aRow + 64] = a1.z;
        As[aCol + 3][aRow + 64] = a1.w;
        float4 bv = *(const float4*)(W + (size_t)(kt + bRow) * Dd + colBase + bCol);
        *(float4*)&Bs[bRow][bCol] = bv;
        __syncthreads();

#pragma unroll
        for (int k = 0; k < 16; k++) {
            float ar[8], br[4];
            *(float4*)(ar)     = *(const float4*)&As[k][ty * 8];
            *(float4*)(ar + 4) = *(const float4*)&As[k][ty * 8 + 4];
            *(float4*)(br)     = *(const float4*)&Bs[k][tx * 4];
#pragma unroll
            for (int i = 0; i < 8; i++)
#pragma unroll
                for (int j = 0; j < 4; j++)
                    acc[i][j] = fmaf(ar[i], br[j], acc[i][j]);
        }
        __syncthreads();
    }

#pragma unroll
    for (int i = 0; i < 8; i++) {
        int row = rowBase + ty * 8 + i;
        int t   = row & (Tt - 1);           // row = b*T + t, T pow2
        const float* fr = freq + (size_t)t * Dd;
#pragma unroll
        for (int j = 0; j < 4; j++) {
            int col = colBase + tx * 4 + j;
            g_h[(size_t)row * Dd + col] = acc[i][j] + bias[col] + fr[col];
        }
    }
}

// ---------------------------------------------------------------------------
// Fused S4 layer: one block owns (b, DBLK d-channels, all 64 chunks).
//   phase 1: per-chunk scan from zero -> chunk-final states into smem
//   phase 2: 64-step chunk recurrence, in smem (no DRAM round trip)
//   phase 3: re-scan with correct start states, fused C.x, D_skip, GELU,
//            residual; h updated in place.
// Block = NCH * DBLK = 512 threads.  Grid = B * (D/DBLK) = 256 blocks.
// ---------------------------------------------------------------------------
__global__ __launch_bounds__(512)
void s4_layer_kernel(int l, const float* __restrict__ C_ssm,
                     const float* __restrict__ D_skip) {
    __shared__ float sx[NCH * DBLK * Nn];   // 64*8*16 floats = 32 KB

    int tid  = threadIdx.x;
    int dl   = tid & (DBLK - 1);            // 0..7
    int c    = tid >> 3;                    // 0..63
    int b    = blockIdx.x >> 6;             // grid = b*(D/DBLK)+dblk
    int dblk = blockIdx.x & 63;
    int d    = dblk * DBLK + dl;

    // Per-channel constants
    float ab[16], bb[16];
    {
        const float4* abp = (const float4*)(g_Abar  + (size_t)l * DN + d * Nn);
        const float4* bbp = (const float4*)(g_BbarB + (size_t)l * DN + d * Nn);
#pragma unroll
        for (int q = 0; q < 4; q++) {
            float4 va = abp[q]; float4 vb = bbp[q];
            ab[4*q+0]=va.x; ab[4*q+1]=va.y; ab[4*q+2]=va.z; ab[4*q+3]=va.w;
            bb[4*q+0]=vb.x; bb[4*q+1]=vb.y; bb[4*q+2]=vb.z; bb[4*q+3]=vb.w;
        }
    }

    // ---------------- Phase 1: chunk scan from zero state ----------------
    float x[16];
#pragma unroll
    for (int n = 0; n < 16; n++) x[n] = 0.0f;

    const float* up = g_h + ((size_t)b * Tt + (size_t)c * TC) * Dd + d;
#pragma unroll 4
    for (int i = 0; i < TC; i++) {
        float u = up[(size_t)i * Dd];
#pragma unroll
        for (int n = 0; n < 16; n++)
            x[n] = fmaf(ab[n], x[n], bb[n] * u);
    }

    {
        float4* so = (float4*)&sx[(c * DBLK + dl) * Nn];
#pragma unroll
        for (int q = 0; q < 4; q++)
            so[q] = make_float4(x[4*q+0], x[4*q+1], x[4*q+2], x[4*q+3]);
    }
    __syncthreads();

    // ---------------- Phase 2: recurrence across chunks (in smem) --------
    if (tid < DBLK * Nn) {                  // 128 threads
        int dl2 = tid >> 4;                 // 0..7
        int n2  = tid & 15;
        float ap = g_AbarP[(size_t)l * DN + (dblk * DBLK + dl2) * Nn + n2];
        int base = dl2 * Nn + n2;
        float xs = 0.0f;
#pragma unroll 4
        for (int cc = 0; cc < NCH; cc++) {
            float f = sx[cc * (DBLK * Nn) + base];
            sx[cc * (DBLK * Nn) + base] = xs;     // overwrite with start state
            xs = fmaf(ap, xs, f);
        }
    }
    __syncthreads();

    // ---------------- Phase 3: re-scan + fused epilogue -------------------
    float cv[16];
    {
        const float4* ccp = (const float4*)(C_ssm + (size_t)l * DN + d * Nn);
#pragma unroll
        for (int q = 0; q < 4; q++) {
            float4 vc = ccp[q];
            cv[4*q+0]=vc.x; cv[4*q+1]=vc.y; cv[4*q+2]=vc.z; cv[4*q+3]=vc.w;
        }
    }
    float dsk = D_skip[l * Dd + d];

    {
        const float4* si = (const float4*)&sx[(c * DBLK + dl) * Nn];
#pragma unroll
        for (int q = 0; q < 4; q++) {
            float4 v = si[q];
            x[4*q+0]=v.x; x[4*q+1]=v.y; x[4*q+2]=v.z; x[4*q+3]=v.w;
        }
    }

    float* hp = g_h + ((size_t)b * Tt + (size_t)c * TC) * Dd + d;
#pragma unroll 2
    for (int i = 0; i < TC; i++) {
        float u = hp[(size_t)i * Dd];
        float y = 0.0f;
#pragma unroll
        for (int n = 0; n < 16; n++) {
            x[n] = fmaf(ab[n], x[n], bb[n] * u);
            y = fmaf(x[n], cv[n], y);
        }
        y = fmaf(dsk, u, y);
        // JAX default gelu (tanh approximation)
        float y3 = y * y * y;
        float inner = 0.7978845608028654f * (y + 0.044715f * y3);
        float g = 0.5f * y * (1.0f + tanhf(inner));
        hp[(size_t)i * Dd] = u + g;
    }
}

// ---------------------------------------------------------------------------
// Head: dual LayerNorm + two scalar projections. One block per (b,t) row.
// ---------------------------------------------------------------------------
__device__ __forceinline__ float blockReduce256(float v, float* sh) {
#pragma unroll
    for (int o = 16; o > 0; o >>= 1) v += __shfl_xor_sync(0xffffffffu, v, o);
    int lane = threadIdx.x & 31, w = threadIdx.x >> 5;
    if (lane == 0) sh[w] = v;
    __syncthreads();
    if (w == 0) {
        v = (lane < 8) ? sh[lane] : 0.0f;
#pragma unroll
        for (int o = 4; o > 0; o >>= 1) v += __shfl_xor_sync(0xffffffffu, v, o);
        if (lane == 0) sh[0] = v;
    }
    __syncthreads();
    float r = sh[0];
    __syncthreads();
    return r;
}

__global__ __launch_bounds__(256)
void head_kernel(const float* __restrict__ s_f0, const float* __restrict__ bi_f0,
                 const float* __restrict__ w_f0, const float* __restrict__ b_f0,
                 const float* __restrict__ s_en, const float* __restrict__ bi_en,
                 const float* __restrict__ w_en, const float* __restrict__ b_en,
                 float* __restrict__ out) {
    __shared__ float sh[32];
    int row = blockIdx.x;
    const float* hp = g_h + (size_t)row * Dd;
    int t0 = threadIdx.x, t1 = threadIdx.x + 256;
    float v0 = hp[t0], v1 = hp[t1];

    float s  = blockReduce256(v0 + v1, sh);
    float ss = blockReduce256(v0 * v0 + v1 * v1, sh);
    float mu   = s * (1.0f / Dd);
    float var  = ss * (1.0f / Dd) - mu * mu;
    float rstd = rsqrtf(var + 1e-5f);

    float n0 = (v0 - mu) * rstd, n1 = (v1 - mu) * rstd;
    float f0c = fmaf(n0, s_f0[t0], bi_f0[t0]) * w_f0[t0]
              + fmaf(n1, s_f0[t1], bi_f0[t1]) * w_f0[t1];
    float enc = fmaf(n0, s_en[t0], bi_en[t0]) * w_en[t0]
              + fmaf(n1, s_en[t1], bi_en[t1]) * w_en[t1];

    f0c = blockReduce256(f0c, sh);
    enc = blockReduce256(enc, sh);
    if (threadIdx.x == 0) {
        out[row]                     = f0c + b_f0[0];
        out[(size_t)Bb * Tt + row]   = enc + b_en[0];
    }
}

// ---------------------------------------------------------------------------
extern "C" void kernel_launch(void* const* d_in, const int* in_sizes, int n_in,
                              void* d_out, int out_size) {
    const float* text_emb = (const float*)d_in[0];
    const float* W_in     = (const float*)d_in[1];
    const float* b_in     = (const float*)d_in[2];
    const float* freq_pe  = (const float*)d_in[3];
    const float* A_log    = (const float*)d_in[4];
    const float* B_ssm    = (const float*)d_in[5];
    const float* C_ssm    = (const float*)d_in[6];
    const float* log_dt   = (const float*)d_in[7];
    const float* D_skip   = (const float*)d_in[8];
    const float* ln_f0_s  = (const float*)d_in[9];
    const float* ln_f0_b  = (const float*)d_in[10];
    const float* W_f0     = (const float*)d_in[11];
    const float* b_f0     = (const float*)d_in[12];
    const float* ln_en_s  = (const float*)d_in[13];
    const float* ln_en_b  = (const float*)d_in[14];
    const float* W_en     = (const float*)d_in[15];
    const float* b_en     = (const float*)d_in[16];
    float* out = (float*)d_out;

    precompute_kernel<<<(Ll * DN + 255) / 256, 256>>>(A_log, B_ssm, log_dt);

    dim3 ggrid(Dd / 64, (Bb * Tt) / 128);
    gemm_in_kernel<<<ggrid, 256>>>(text_emb, W_in, b_in, freq_pe);

    for (int l = 0; l < Ll; l++) {
        s4_layer_kernel<<<Bb * (Dd / DBLK), NCH * DBLK>>>(l, C_ssm, D_skip);
    }

    head_kernel<<<Bb * Tt, 256>>>(ln_f0_s, ln_f0_b, W_f0, b_f0,
                                  ln_en_s, ln_en_b, W_en, b_en, out);
}

// round 3
// speedup vs baseline: 1.3583x; 1.0900x over previous
#include <cuda_runtime.h>
#include <math.h>

// Problem constants
#define Bb   4
#define Tt   2048
#define Ee   512
#define Dd   512
#define Nn   16
#define Ll   4
#define TC   32              // chunk length
#define NCH  (Tt / TC)       // 64 chunks
#define DN   (Dd * Nn)       // 8192
#define DBLK 4               // d-channels per block in fused scan
#define SXS  66              // padded smem row stride (floats)

typedef unsigned long long ull;

__device__ __forceinline__ ull pack2(float lo, float hi) {
    ull r; asm("mov.b64 %0, {%1,%2};" : "=l"(r) : "f"(lo), "f"(hi)); return r;
}
__device__ __forceinline__ void unpack2(ull v, float& lo, float& hi) {
    asm("mov.b64 {%0,%1}, %2;" : "=f"(lo), "=f"(hi) : "l"(v));
}
__device__ __forceinline__ ull fma2(ull a, ull b, ull c) {
    ull d; asm("fma.rn.f32x2 %0, %1, %2, %3;" : "=l"(d) : "l"(a), "l"(b), "l"(c));
    return d;
}

// Scratch (static device globals; no runtime allocation)
__device__ float g_h[(size_t)Bb * Tt * Dd];        // residual stream, 16 MB
__device__ float g_Abar [Ll * DN];
__device__ float g_CB   [Ll * DN];                 // C * Bbar
__device__ float g_AbarP[Ll * DN];                 // Abar^TC

// ---------------------------------------------------------------------------
// Precompute per-layer SSM constants
// ---------------------------------------------------------------------------
__global__ void precompute_kernel(const float* __restrict__ A_log,
                                  const float* __restrict__ B_ssm,
                                  const float* __restrict__ C_ssm,
                                  const float* __restrict__ log_dt) {
    int idx = blockIdx.x * blockDim.x + threadIdx.x;
    if (idx >= Ll * DN) return;
    int l  = idx / DN;
    int dn = idx % DN;
    int d  = dn / Nn;
    float dt = expf(log_dt[l * Dd + d]);
    float A  = -expf(A_log[idx]);
    float dA = dt * A;
    float ab = expf(dA);
    g_Abar [idx] = ab;
    g_CB   [idx] = (ab - 1.0f) / A * B_ssm[idx] * C_ssm[idx];
    g_AbarP[idx] = expf(dA * (float)TC);
}

// ---------------------------------------------------------------------------
// Input GEMM (double-buffered): h = X@W + b_in + freq
// M=8192, K=512, N=512.  BM=128, BN=64, BK=16, TM=8, TN=4, 256 threads.
// ---------------------------------------------------------------------------
__global__ __launch_bounds__(256)
void gemm_in_kernel(const float* __restrict__ X, const float* __restrict__ W,
                    const float* __restrict__ bias, const float* __restrict__ freq) {
    __shared__ float As[2][16][128];
    __shared__ float Bs[2][16][64];

    int tid = threadIdx.x;
    int tx = tid & 15;
    int ty = tid >> 4;
    int rowBase = blockIdx.y * 128;
    int colBase = blockIdx.x * 64;

    float acc[8][4];
#pragma unroll
    for (int i = 0; i < 8; i++)
#pragma unroll
        for (int j = 0; j < 4; j++) acc[i][j] = 0.0f;

    int aRow = tid >> 2;            // 0..63
    int aCol = (tid & 3) << 2;      // 0,4,8,12
    int bRow = tid >> 4;            // 0..15
    int bCol = (tid & 15) << 2;     // 0..60

    const float* Xp = X + (size_t)rowBase * Ee;

    float4 pa0 = *(const float4*)(Xp + (size_t)aRow        * Ee + aCol);
    float4 pa1 = *(const float4*)(Xp + (size_t)(aRow + 64) * Ee + aCol);
    float4 pb  = *(const float4*)(W + (size_t)bRow * Dd + colBase + bCol);

    As[0][aCol + 0][aRow]      = pa0.x;
    As[0][aCol + 1][aRow]      = pa0.y;
    As[0][aCol + 2][aRow]      = pa0.z;
    As[0][aCol + 3][aRow]      = pa0.w;
    As[0][aCol + 0][aRow + 64] = pa1.x;
    As[0][aCol + 1][aRow + 64] = pa1.y;
    As[0][aCol + 2][aRow + 64] = pa1.z;
    As[0][aCol + 3][aRow + 64] = pa1.w;
    *(float4*)&Bs[0][bRow][bCol] = pb;
    __syncthreads();

    int buf = 0;
    for (int kt = 16; kt < Ee; kt += 16) {
        // prefetch next tile
        pa0 = *(const float4*)(Xp + (size_t)aRow        * Ee + kt + aCol);
        pa1 = *(const float4*)(Xp + (size_t)(aRow + 64) * Ee + kt + aCol);
        pb  = *(const float4*)(W + (size_t)(kt + bRow) * Dd + colBase + bCol);

#pragma unroll
        for (int k = 0; k < 16; k++) {
            float ar[8], br[4];
            *(float4*)(ar)     = *(const float4*)&As[buf][k][ty * 8];
            *(float4*)(ar + 4) = *(const float4*)&As[buf][k][ty * 8 + 4];
            *(float4*)(br)     = *(const float4*)&Bs[buf][k][tx * 4];
#pragma unroll
            for (int i = 0; i < 8; i++)
#pragma unroll
                for (int j = 0; j < 4; j++)
                    acc[i][j] = fmaf(ar[i], br[j], acc[i][j]);
        }

        int nb = buf ^ 1;
        As[nb][aCol + 0][aRow]      = pa0.x;
        As[nb][aCol + 1][aRow]      = pa0.y;
        As[nb][aCol + 2][aRow]      = pa0.z;
        As[nb][aCol + 3][aRow]      = pa0.w;
        As[nb][aCol + 0][aRow + 64] = pa1.x;
        As[nb][aCol + 1][aRow + 64] = pa1.y;
        As[nb][aCol + 2][aRow + 64] = pa1.z;
        As[nb][aCol + 3][aRow + 64] = pa1.w;
        *(float4*)&Bs[nb][bRow][bCol] = pb;
        __syncthreads();
        buf = nb;
    }

#pragma unroll
    for (int k = 0; k < 16; k++) {
        float ar[8], br[4];
        *(float4*)(ar)     = *(const float4*)&As[buf][k][ty * 8];
        *(float4*)(ar + 4) = *(const float4*)&As[buf][k][ty * 8 + 4];
        *(float4*)(br)     = *(const float4*)&Bs[buf][k][tx * 4];
#pragma unroll
        for (int i = 0; i < 8; i++)
#pragma unroll
            for (int j = 0; j < 4; j++)
                acc[i][j] = fmaf(ar[i], br[j], acc[i][j]);
    }

#pragma unroll
    for (int i = 0; i < 8; i++) {
        int row = rowBase + ty * 8 + i;
        int t   = row & (Tt - 1);
        const float* fr = freq + (size_t)t * Dd;
#pragma unroll
        for (int j = 0; j < 4; j++) {
            int col = colBase + tx * 4 + j;
            g_h[(size_t)row * Dd + col] = acc[i][j] + bias[col] + fr[col];
        }
    }
}

// ---------------------------------------------------------------------------
// Fused S4 layer, z-form (z = a z + u; y = dot(cb, z)), packed f32x2.
// Block = 256 threads: (c 0..63) x (dl 0..3).  Grid = B * (D/DBLK) = 512.
// Phase 2: 4-segment shuffle scan over 64 chunks (all 256 threads active).
// ---------------------------------------------------------------------------
__global__ __launch_bounds__(256)
void s4_layer_kernel(int l, const float* __restrict__ D_skip) {
    __shared__ float sx[NCH * SXS];         // 64*66*4 = 16.9 KB

    int tid  = threadIdx.x;
    int dl   = tid & (DBLK - 1);            // 0..3
    int c    = tid >> 2;                    // 0..63
    int b    = blockIdx.x >> 7;
    int dblk = blockIdx.x & 127;
    int d    = dblk * DBLK + dl;

    // Per-channel decay constants (packed pairs)
    ull a2[8];
    {
        const float4* ap4 = (const float4*)(g_Abar + (size_t)l * DN + d * Nn);
#pragma unroll
        for (int q = 0; q < 4; q++) {
            float4 v = ap4[q];
            a2[2*q]   = pack2(v.x, v.y);
            a2[2*q+1] = pack2(v.z, v.w);
        }
    }

    // ---------------- Phase 1: chunk scan from zero (z-form) -------------
    ull z2[8];
#pragma unroll
    for (int q = 0; q < 8; q++) z2[q] = 0ull;

    const float* up = g_h + ((size_t)b * Tt + (size_t)c * TC) * Dd + d;
#pragma unroll 4
    for (int i = 0; i < TC; i++) {
        float u = up[(size_t)i * Dd];
        ull u2 = pack2(u, u);
#pragma unroll
        for (int q = 0; q < 8; q++)
            z2[q] = fma2(a2[q], z2[q], u2);
    }

    {
        ull* so = (ull*)(sx + c * SXS + dl * Nn);
#pragma unroll
        for (int q = 0; q < 8; q++) so[q] = z2[q];
    }
    __syncthreads();

    // ---------------- Phase 2: shuffle scan across 64 chunks -------------
    {
        int seg = tid & 3;                  // 0..3 (lane bits [1:0])
        int dn  = tid >> 2;                 // 0..63  (dl2*16 + n)
        int dl2 = dn >> 4, n2 = dn & 15;
        float ap = g_AbarP[(size_t)l * DN + (dblk * DBLK + dl2) * Nn + n2];

        float f[16];
#pragma unroll
        for (int j = 0; j < 16; j++)
            f[j] = sx[(seg * 16 + j) * SXS + dn];

        // segment-local reduce: F = sum_j ap^(15-j) f_j
        float F = 0.0f;
#pragma unroll
        for (int j = 0; j < 16; j++) F = fmaf(ap, F, f[j]);

        float p2 = ap * ap, p4 = p2 * p2, p8 = p4 * p4;
        float m  = p8 * p8;                 // ap^16

        // Kogge-Stone inclusive scan over 4 segments (width-4 shuffles)
        float Fp = __shfl_up_sync(0xffffffffu, F, 1, 4);
        float mp = __shfl_up_sync(0xffffffffu, m, 1, 4);
        if (seg >= 1) { F = fmaf(m, Fp, F); m *= mp; }
        Fp = __shfl_up_sync(0xffffffffu, F, 2, 4);
        mp = __shfl_up_sync(0xffffffffu, m, 2, 4);
        if (seg >= 2) { F = fmaf(m, Fp, F); m *= mp; }

        float carry = __shfl_up_sync(0xffffffffu, F, 1, 4);
        if (seg == 0) carry = 0.0f;

        float xs = carry;
#pragma unroll
        for (int j = 0; j < 16; j++) {
            sx[(seg * 16 + j) * SXS + dn] = xs;     // start state of chunk
            xs = fmaf(ap, xs, f[j]);
        }
    }
    __syncthreads();

    // ---------------- Phase 3: re-scan + fused epilogue -------------------
    ull cb2[8];
    {
        const float4* cp4 = (const float4*)(g_CB + (size_t)l * DN + d * Nn);
#pragma unroll
        for (int q = 0; q < 4; q++) {
            float4 v = cp4[q];
            cb2[2*q]   = pack2(v.x, v.y);
            cb2[2*q+1] = pack2(v.z, v.w);
        }
    }
    float dsk = D_skip[l * Dd + d];

    {
        const ull* si = (const ull*)(sx + c * SXS + dl * Nn);
#pragma unroll
        for (int q = 0; q < 8; q++) z2[q] = si[q];
    }

    float* hp = g_h + ((size_t)b * Tt + (size_t)c * TC) * Dd + d;
#pragma unroll 2
    for (int i = 0; i < TC; i++) {
        float u = hp[(size_t)i * Dd];
        ull u2 = pack2(u, u);
        ull y2 = 0ull;
#pragma unroll
        for (int q = 0; q < 8; q++) {
            z2[q] = fma2(a2[q], z2[q], u2);
            y2 = fma2(z2[q], cb2[q], y2);
        }
        float ylo, yhi; unpack2(y2, ylo, yhi);
        float y = ylo + yhi;
        y = fmaf(dsk, u, y);
        // gelu(y) = y * sigmoid(2 * 0.79788456*(y + 0.044715 y^3))
        float yy = y * y;
        float inner2 = 1.5957691216057308f * (y + 0.044715f * y * yy);
        float e = __expf(-inner2);
        float g = __fdividef(y, 1.0f + e);
        hp[(size_t)i * Dd] = u + g;
    }
}

// ---------------------------------------------------------------------------
// Head: dual LayerNorm + two scalar projections. One block per (b,t) row.
// ---------------------------------------------------------------------------
__device__ __forceinline__ float blockReduce256(float v, float* sh) {
#pragma unroll
    for (int o = 16; o > 0; o >>= 1) v += __shfl_xor_sync(0xffffffffu, v, o);
    int lane = threadIdx.x & 31, w = threadIdx.x >> 5;
    if (lane == 0) sh[w] = v;
    __syncthreads();
    if (w == 0) {
        v = (lane < 8) ? sh[lane] : 0.0f;
#pragma unroll
        for (int o = 4; o > 0; o >>= 1) v += __shfl_xor_sync(0xffffffffu, v, o);
        if (lane == 0) sh[0] = v;
    }
    __syncthreads();
    float r = sh[0];
    __syncthreads();
    return r;
}

__global__ __launch_bounds__(256)
void head_kernel(const float* __restrict__ s_f0, const float* __restrict__ bi_f0,
                 const float* __restrict__ w_f0, const float* __restrict__ b_f0,
                 const float* __restrict__ s_en, const float* __restrict__ bi_en,
                 const float* __restrict__ w_en, const float* __restrict__ b_en,
                 float* __restrict__ out) {
    __shared__ float sh[32];
    int row = blockIdx.x;
    const float* hp = g_h + (size_t)row * Dd;
    int t0 = threadIdx.x, t1 = threadIdx.x + 256;
    float v0 = hp[t0], v1 = hp[t1];

    float s  = blockReduce256(v0 + v1, sh);
    float ss = blockReduce256(v0 * v0 + v1 * v1, sh);
    float mu   = s * (1.0f / Dd);
    float var  = ss * (1.0f / Dd) - mu * mu;
    float rstd = rsqrtf(var + 1e-5f);

    float n0 = (v0 - mu) * rstd, n1 = (v1 - mu) * rstd;
    float f0c = fmaf(n0, s_f0[t0], bi_f0[t0]) * w_f0[t0]
              + fmaf(n1, s_f0[t1], bi_f0[t1]) * w_f0[t1];
    float enc = fmaf(n0, s_en[t0], bi_en[t0]) * w_en[t0]
              + fmaf(n1, s_en[t1], bi_en[t1]) * w_en[t1];

    f0c = blockReduce256(f0c, sh);
    enc = blockReduce256(enc, sh);
    if (threadIdx.x == 0) {
        out[row]                     = f0c + b_f0[0];
        out[(size_t)Bb * Tt + row]   = enc + b_en[0];
    }
}

// ---------------------------------------------------------------------------
extern "C" void kernel_launch(void* const* d_in, const int* in_sizes, int n_in,
                              void* d_out, int out_size) {
    const float* text_emb = (const float*)d_in[0];
    const float* W_in     = (const float*)d_in[1];
    const float* b_in     = (const float*)d_in[2];
    const float* freq_pe  = (const float*)d_in[3];
    const float* A_log    = (const float*)d_in[4];
    const float* B_ssm    = (const float*)d_in[5];
    const float* C_ssm    = (const float*)d_in[6];
    const float* log_dt   = (const float*)d_in[7];
    const float* D_skip   = (const float*)d_in[8];
    const float* ln_f0_s  = (const float*)d_in[9];
    const float* ln_f0_b  = (const float*)d_in[10];
    const float* W_f0     = (const float*)d_in[11];
    const float* b_f0     = (const float*)d_in[12];
    const float* ln_en_s  = (const float*)d_in[13];
    const float* ln_en_b  = (const float*)d_in[14];
    const float* W_en     = (const float*)d_in[15];
    const float* b_en     = (const float*)d_in[16];
    float* out = (float*)d_out;

    precompute_kernel<<<(Ll * DN + 255) / 256, 256>>>(A_log, B_ssm, C_ssm, log_dt);

    dim3 ggrid(Dd / 64, (Bb * Tt) / 128);
    gemm_in_kernel<<<ggrid, 256>>>(text_emb, W_in, b_in, freq_pe);

    for (int l = 0; l < Ll; l++) {
        s4_layer_kernel<<<Bb * (Dd / DBLK), 256>>>(l, D_skip);
    }

    head_kernel<<<Bb * Tt, 256>>>(ln_f0_s, ln_f0_b, W_f0, b_f0,
                                  ln_en_s, ln_en_b, W_en, b_en, out);
}

// round 4
// speedup vs baseline: 1.9117x; 1.4074x over previous
#include <cuda_runtime.h>
#include <math.h>

// Problem constants
#define Bb   4
#define Tt   2048
#define Ee   512
#define Dd   512
#define Nn   16
#define Ll   4
#define TC   32              // chunk length (time steps per thread)
#define NCH  (Tt / TC)       // 64 chunks
#define DN   (Dd * Nn)       // 8192
#define DBLK 4               // d-channels per block in fused scan
#define SXS  66              // padded smem row stride (floats)

typedef unsigned long long ull;

__device__ __forceinline__ ull pack2(float lo, float hi) {
    ull r; asm("mov.b64 %0, {%1,%2};" : "=l"(r) : "f"(lo), "f"(hi)); return r;
}
__device__ __forceinline__ void unpack2(ull v, float& lo, float& hi) {
    asm("mov.b64 {%0,%1}, %2;" : "=f"(lo), "=f"(hi) : "l"(v));
}
__device__ __forceinline__ ull fma2(ull a, ull b, ull c) {
    ull d; asm("fma.rn.f32x2 %0, %1, %2, %3;" : "=l"(d) : "l"(a), "l"(b), "l"(c));
    return d;
}

// Scratch (static device globals; no runtime allocation)
__device__ float g_h[(size_t)Bb * Tt * Dd];        // residual stream, 16 MB
__device__ float g_Abar [Ll * DN];
__device__ float g_CB   [Ll * DN];                 // C * Bbar
__device__ float g_AbarP[Ll * DN];                 // Abar^TC

// ---------------------------------------------------------------------------
// Precompute per-layer SSM constants
// ---------------------------------------------------------------------------
__global__ void precompute_kernel(const float* __restrict__ A_log,
                                  const float* __restrict__ B_ssm,
                                  const float* __restrict__ C_ssm,
                                  const float* __restrict__ log_dt) {
    int idx = blockIdx.x * blockDim.x + threadIdx.x;
    if (idx >= Ll * DN) return;
    int l  = idx / DN;
    int dn = idx % DN;
    int d  = dn / Nn;
    float dt = expf(log_dt[l * Dd + d]);
    float A  = -expf(A_log[idx]);
    float dA = dt * A;
    float ab = expf(dA);
    g_Abar [idx] = ab;
    g_CB   [idx] = (ab - 1.0f) / A * B_ssm[idx] * C_ssm[idx];
    g_AbarP[idx] = expf(dA * (float)TC);
}

// ---------------------------------------------------------------------------
// Input GEMM (double-buffered): h = X@W + b_in + freq
// M=8192, K=512, N=512.  BM=128, BN=64, BK=16, TM=8, TN=4, 256 threads.
// ---------------------------------------------------------------------------
__global__ __launch_bounds__(256)
void gemm_in_kernel(const float* __restrict__ X, const float* __restrict__ W,
                    const float* __restrict__ bias, const float* __restrict__ freq) {
    __shared__ float As[2][16][128];
    __shared__ float Bs[2][16][64];

    int tid = threadIdx.x;
    int tx = tid & 15;
    int ty = tid >> 4;
    int rowBase = blockIdx.y * 128;
    int colBase = blockIdx.x * 64;

    float acc[8][4];
#pragma unroll
    for (int i = 0; i < 8; i++)
#pragma unroll
        for (int j = 0; j < 4; j++) acc[i][j] = 0.0f;

    int aRow = tid >> 2;            // 0..63
    int aCol = (tid & 3) << 2;      // 0,4,8,12
    int bRow = tid >> 4;            // 0..15
    int bCol = (tid & 15) << 2;     // 0..60

    const float* Xp = X + (size_t)rowBase * Ee;

    float4 pa0 = *(const float4*)(Xp + (size_t)aRow        * Ee + aCol);
    float4 pa1 = *(const float4*)(Xp + (size_t)(aRow + 64) * Ee + aCol);
    float4 pb  = *(const float4*)(W + (size_t)bRow * Dd + colBase + bCol);

    As[0][aCol + 0][aRow]      = pa0.x;
    As[0][aCol + 1][aRow]      = pa0.y;
    As[0][aCol + 2][aRow]      = pa0.z;
    As[0][aCol + 3][aRow]      = pa0.w;
    As[0][aCol + 0][aRow + 64] = pa1.x;
    As[0][aCol + 1][aRow + 64] = pa1.y;
    As[0][aCol + 2][aRow + 64] = pa1.z;
    As[0][aCol + 3][aRow + 64] = pa1.w;
    *(float4*)&Bs[0][bRow][bCol] = pb;
    __syncthreads();

    int buf = 0;
    for (int kt = 16; kt < Ee; kt += 16) {
        pa0 = *(const float4*)(Xp + (size_t)aRow        * Ee + kt + aCol);
        pa1 = *(const float4*)(Xp + (size_t)(aRow + 64) * Ee + kt + aCol);
        pb  = *(const float4*)(W + (size_t)(kt + bRow) * Dd + colBase + bCol);

#pragma unroll
        for (int k = 0; k < 16; k++) {
            float ar[8], br[4];
            *(float4*)(ar)     = *(const float4*)&As[buf][k][ty * 8];
            *(float4*)(ar + 4) = *(const float4*)&As[buf][k][ty * 8 + 4];
            *(float4*)(br)     = *(const float4*)&Bs[buf][k][tx * 4];
#pragma unroll
            for (int i = 0; i < 8; i++)
#pragma unroll
                for (int j = 0; j < 4; j++)
                    acc[i][j] = fmaf(ar[i], br[j], acc[i][j]);
        }

        int nb = buf ^ 1;
        As[nb][aCol + 0][aRow]      = pa0.x;
        As[nb][aCol + 1][aRow]      = pa0.y;
        As[nb][aCol + 2][aRow]      = pa0.z;
        As[nb][aCol + 3][aRow]      = pa0.w;
        As[nb][aCol + 0][aRow + 64] = pa1.x;
        As[nb][aCol + 1][aRow + 64] = pa1.y;
        As[nb][aCol + 2][aRow + 64] = pa1.z;
        As[nb][aCol + 3][aRow + 64] = pa1.w;
        *(float4*)&Bs[nb][bRow][bCol] = pb;
        __syncthreads();
        buf = nb;
    }

#pragma unroll
    for (int k = 0; k < 16; k++) {
        float ar[8], br[4];
        *(float4*)(ar)     = *(const float4*)&As[buf][k][ty * 8];
        *(float4*)(ar + 4) = *(const float4*)&As[buf][k][ty * 8 + 4];
        *(float4*)(br)     = *(const float4*)&Bs[buf][k][tx * 4];
#pragma unroll
        for (int i = 0; i < 8; i++)
#pragma unroll
            for (int j = 0; j < 4; j++)
                acc[i][j] = fmaf(ar[i], br[j], acc[i][j]);
    }

#pragma unroll
    for (int i = 0; i < 8; i++) {
        int row = rowBase + ty * 8 + i;
        int t   = row & (Tt - 1);
        const float* fr = freq + (size_t)t * Dd;
#pragma unroll
        for (int j = 0; j < 4; j++) {
            int col = colBase + tx * 4 + j;
            g_h[(size_t)row * Dd + col] = acc[i][j] + bias[col] + fr[col];
        }
    }
}

// ---------------------------------------------------------------------------
// Fused 4-layer S4 stack. One block owns (b, DBLK channels, all T).
// u kept in registers across all layers; zero inter-layer global traffic.
// Block = 256 threads: thread (c 0..63, dl 0..3) owns chunk c of channel dl.
// Grid = B * (D/DBLK) = 512 blocks.
// ---------------------------------------------------------------------------
__global__ __launch_bounds__(256)
void s4_stack_kernel(const float* __restrict__ D_skip) {
    __shared__ float sx[NCH * SXS];         // 64*66*4 = 16.9 KB

    int tid  = threadIdx.x;
    int dl   = tid & (DBLK - 1);            // 0..3
    int c    = tid >> 2;                    // 0..63
    int b    = blockIdx.x >> 7;
    int dblk = blockIdx.x & 127;
    int d    = dblk * DBLK + dl;

    // phase-2 mapping (per-thread constants)
    int seg = tid & 3;                      // 0..3
    int dn  = tid >> 2;                     // 0..63
    int dl2 = dn >> 4, n2 = dn & 15;

    // Load this thread's 32 time steps of u into registers (strided, once)
    float u[TC];
    float* hp = g_h + ((size_t)b * Tt + (size_t)c * TC) * Dd + d;
#pragma unroll
    for (int i = 0; i < TC; i++) u[i] = hp[(size_t)i * Dd];

    for (int l = 0; l < Ll; l++) {
        // Per-channel decay constants (packed pairs)
        ull a2[8];
        {
            const float4* ap4 = (const float4*)(g_Abar + (size_t)l * DN + d * Nn);
#pragma unroll
            for (int q = 0; q < 4; q++) {
                float4 v = ap4[q];
                a2[2*q]   = pack2(v.x, v.y);
                a2[2*q+1] = pack2(v.z, v.w);
            }
        }

        // ---------------- Phase 1: chunk scan from zero (z-form) ---------
        ull z2[8];
#pragma unroll
        for (int q = 0; q < 8; q++) z2[q] = 0ull;
#pragma unroll
        for (int i = 0; i < TC; i++) {
            ull u2 = pack2(u[i], u[i]);
#pragma unroll
            for (int q = 0; q < 8; q++)
                z2[q] = fma2(a2[q], z2[q], u2);
        }
        {
            ull* so = (ull*)(sx + c * SXS + dl * Nn);
#pragma unroll
            for (int q = 0; q < 8; q++) so[q] = z2[q];
        }
        __syncthreads();

        // ---------------- Phase 2: shuffle scan across 64 chunks ---------
        {
            float ap = g_AbarP[(size_t)l * DN + (dblk * DBLK + dl2) * Nn + n2];

            float f[16];
#pragma unroll
            for (int j = 0; j < 16; j++)
                f[j] = sx[(seg * 16 + j) * SXS + dn];

            float F = 0.0f;
#pragma unroll
            for (int j = 0; j < 16; j++) F = fmaf(ap, F, f[j]);

            float p2 = ap * ap, p4 = p2 * p2, p8 = p4 * p4;
            float m  = p8 * p8;              // ap^16

            float Fp = __shfl_up_sync(0xffffffffu, F, 1, 4);
            float mp = __shfl_up_sync(0xffffffffu, m, 1, 4);
            if (seg >= 1) { F = fmaf(m, Fp, F); m *= mp; }
            Fp = __shfl_up_sync(0xffffffffu, F, 2, 4);
            mp = __shfl_up_sync(0xffffffffu, m, 2, 4);
            if (seg >= 2) { F = fmaf(m, Fp, F); m *= mp; }

            float carry = __shfl_up_sync(0xffffffffu, F, 1, 4);
            if (seg == 0) carry = 0.0f;

            float xs = carry;
#pragma unroll
            for (int j = 0; j < 16; j++) {
                sx[(seg * 16 + j) * SXS + dn] = xs;   // chunk start state
                xs = fmaf(ap, xs, f[j]);
            }
        }
        __syncthreads();

        // ---------------- Phase 3: re-scan + fused epilogue (u in regs) ---
        ull cb2[8];
        {
            const float4* cp4 = (const float4*)(g_CB + (size_t)l * DN + d * Nn);
#pragma unroll
            for (int q = 0; q < 4; q++) {
                float4 v = cp4[q];
                cb2[2*q]   = pack2(v.x, v.y);
                cb2[2*q+1] = pack2(v.z, v.w);
            }
        }
        float dsk = D_skip[l * Dd + d];

        {
            const ull* si = (const ull*)(sx + c * SXS + dl * Nn);
#pragma unroll
            for (int q = 0; q < 8; q++) z2[q] = si[q];
        }

#pragma unroll
        for (int i = 0; i < TC; i++) {
            float uu = u[i];
            ull u2 = pack2(uu, uu);
            ull y2 = 0ull;
#pragma unroll
            for (int q = 0; q < 8; q++) {
                z2[q] = fma2(a2[q], z2[q], u2);
                y2 = fma2(z2[q], cb2[q], y2);
            }
            float ylo, yhi; unpack2(y2, ylo, yhi);
            float y = ylo + yhi;
            y = fmaf(dsk, uu, y);
            // gelu(y) = y * sigmoid(2 * 0.79788456*(y + 0.044715 y^3))
            float yy = y * y;
            float inner2 = 1.5957691216057308f * (y + 0.044715f * y * yy);
            float e = __expf(-inner2);
            float g = __fdividef(y, 1.0f + e);
            u[i] = uu + g;
        }
        // No extra sync needed: the smem cells this thread rewrites in the
        // next layer's phase 1 are the same ones only THIS thread read above.
    }

    // Write final residual stream back (once)
#pragma unroll
    for (int i = 0; i < TC; i++) hp[(size_t)i * Dd] = u[i];
}

// ---------------------------------------------------------------------------
// Head: dual LayerNorm + two scalar projections. One block per (b,t) row.
// ---------------------------------------------------------------------------
__device__ __forceinline__ float blockReduce256(float v, float* sh) {
#pragma unroll
    for (int o = 16; o > 0; o >>= 1) v += __shfl_xor_sync(0xffffffffu, v, o);
    int lane = threadIdx.x & 31, w = threadIdx.x >> 5;
    if (lane == 0) sh[w] = v;
    __syncthreads();
    if (w == 0) {
        v = (lane < 8) ? sh[lane] : 0.0f;
#pragma unroll
        for (int o = 4; o > 0; o >>= 1) v += __shfl_xor_sync(0xffffffffu, v, o);
        if (lane == 0) sh[0] = v;
    }
    __syncthreads();
    float r = sh[0];
    __syncthreads();
    return r;
}

__global__ __launch_bounds__(256)
void head_kernel(const float* __restrict__ s_f0, const float* __restrict__ bi_f0,
                 const float* __restrict__ w_f0, const float* __restrict__ b_f0,
                 const float* __restrict__ s_en, const float* __restrict__ bi_en,
                 const float* __restrict__ w_en, const float* __restrict__ b_en,
                 float* __restrict__ out) {
    __shared__ float sh[32];
    int row = blockIdx.x;
    const float* hp = g_h + (size_t)row * Dd;
    int t0 = threadIdx.x, t1 = threadIdx.x + 256;
    float v0 = hp[t0], v1 = hp[t1];

    float s  = blockReduce256(v0 + v1, sh);
    float ss = blockReduce256(v0 * v0 + v1 * v1, sh);
    float mu   = s * (1.0f / Dd);
    float var  = ss * (1.0f / Dd) - mu * mu;
    float rstd = rsqrtf(var + 1e-5f);

    float n0 = (v0 - mu) * rstd, n1 = (v1 - mu) * rstd;
    float f0c = fmaf(n0, s_f0[t0], bi_f0[t0]) * w_f0[t0]
              + fmaf(n1, s_f0[t1], bi_f0[t1]) * w_f0[t1];
    float enc = fmaf(n0, s_en[t0], bi_en[t0]) * w_en[t0]
              + fmaf(n1, s_en[t1], bi_en[t1]) * w_en[t1];

    f0c = blockReduce256(f0c, sh);
    enc = blockReduce256(enc, sh);
    if (threadIdx.x == 0) {
        out[row]                     = f0c + b_f0[0];
        out[(size_t)Bb * Tt + row]   = enc + b_en[0];
    }
}

// ---------------------------------------------------------------------------
extern "C" void kernel_launch(void* const* d_in, const int* in_sizes, int n_in,
                              void* d_out, int out_size) {
    const float* text_emb = (const float*)d_in[0];
    const float* W_in     = (const float*)d_in[1];
    const float* b_in     = (const float*)d_in[2];
    const float* freq_pe  = (const float*)d_in[3];
    const float* A_log    = (const float*)d_in[4];
    const float* B_ssm    = (const float*)d_in[5];
    const float* C_ssm    = (const float*)d_in[6];
    const float* log_dt   = (const float*)d_in[7];
    const float* D_skip   = (const float*)d_in[8];
    const float* ln_f0_s  = (const float*)d_in[9];
    const float* ln_f0_b  = (const float*)d_in[10];
    const float* W_f0     = (const float*)d_in[11];
    const float* b_f0     = (const float*)d_in[12];
    const float* ln_en_s  = (const float*)d_in[13];
    const float* ln_en_b  = (const float*)d_in[14];
    const float* W_en     = (const float*)d_in[15];
    const float* b_en     = (const float*)d_in[16];
    float* out = (float*)d_out;

    precompute_kernel<<<(Ll * DN + 255) / 256, 256>>>(A_log, B_ssm, C_ssm, log_dt);

    dim3 ggrid(Dd / 64, (Bb * Tt) / 128);
    gemm_in_kernel<<<ggrid, 256>>>(text_emb, W_in, b_in, freq_pe);

    s4_stack_kernel<<<Bb * (Dd / DBLK), 256>>>(D_skip);

    head_kernel<<<Bb * Tt, 256>>>(ln_f0_s, ln_f0_b, W_f0, b_f0,
                                  ln_en_s, ln_en_b, W_en, b_en, out);
}

// round 5
// speedup vs baseline: 2.9107x; 1.5226x over previous
#include <cuda_runtime.h>
#include <math.h>
#include <stdint.h>

// Problem constants
#define Bb   4
#define Tt   2048
#define Ee   512
#define Dd   512
#define Nn   16
#define Ll   4
#define TC   32              // chunk length (time steps per thread)
#define NCH  (Tt / TC)       // 64 chunks
#define DN   (Dd * Nn)       // 8192
#define DBLK 4               // d-channels per block in fused scan
#define SXS  66              // padded smem row stride (floats)

typedef unsigned long long ull;

__device__ __forceinline__ ull pack2(float lo, float hi) {
    ull r; asm("mov.b64 %0, {%1,%2};" : "=l"(r) : "f"(lo), "f"(hi)); return r;
}
__device__ __forceinline__ void unpack2(ull v, float& lo, float& hi) {
    asm("mov.b64 {%0,%1}, %2;" : "=f"(lo), "=f"(hi) : "l"(v));
}
__device__ __forceinline__ ull fma2(ull a, ull b, ull c) {
    ull d; asm("fma.rn.f32x2 %0, %1, %2, %3;" : "=l"(d) : "l"(a), "l"(b), "l"(c));
    return d;
}
__device__ __forceinline__ uint32_t f2tf(float f) {
    uint32_t u; asm("cvt.rna.tf32.f32 %0, %1;" : "=r"(u) : "f"(f)); return u;
}
__device__ __forceinline__ void ldsm4(uint32_t& r0, uint32_t& r1, uint32_t& r2,
                                      uint32_t& r3, const uint32_t* p) {
    uint32_t a = (uint32_t)__cvta_generic_to_shared(p);
    asm volatile("ldmatrix.sync.aligned.m8n8.x4.shared.b16 {%0,%1,%2,%3}, [%4];"
                 : "=r"(r0), "=r"(r1), "=r"(r2), "=r"(r3) : "r"(a));
}
__device__ __forceinline__ void mma_tf32(float* c, const uint32_t* a,
                                         uint32_t b0, uint32_t b1) {
    asm volatile("mma.sync.aligned.m16n8k8.row.col.f32.tf32.tf32.f32 "
                 "{%0,%1,%2,%3}, {%4,%5,%6,%7}, {%8,%9}, {%0,%1,%2,%3};"
                 : "+f"(c[0]), "+f"(c[1]), "+f"(c[2]), "+f"(c[3])
                 : "r"(a[0]), "r"(a[1]), "r"(a[2]), "r"(a[3]), "r"(b0), "r"(b1));
}

// Scratch (static device globals; no runtime allocation)
__device__ float g_ht[(size_t)Bb * Dd * Tt];       // residual stream, TRANSPOSED [b][d][t]
__device__ float g_Abar [Ll * DN];
__device__ float g_CB   [Ll * DN];                 // C * Bbar
__device__ float g_AbarP[Ll * DN];                 // Abar^TC
__device__ float g_swf0[Dd], g_swen[Dd];           // scale*weight per head
__device__ float g_hc[4];                          // SWf0, BWf0, SWen, BWen

// ---------------------------------------------------------------------------
// Precompute per-layer SSM constants
// ---------------------------------------------------------------------------
__global__ void precompute_kernel(const float* __restrict__ A_log,
                                  const float* __restrict__ B_ssm,
                                  const float* __restrict__ C_ssm,
                                  const float* __restrict__ log_dt) {
    int idx = blockIdx.x * blockDim.x + threadIdx.x;
    if (idx >= Ll * DN) return;
    int l  = idx / DN;
    int dn = idx % DN;
    int d  = dn / Nn;
    float dt = expf(log_dt[l * Dd + d]);
    float A  = -expf(A_log[idx]);
    float dA = dt * A;
    float ab = expf(dA);
    g_Abar [idx] = ab;
    g_CB   [idx] = (ab - 1.0f) / A * B_ssm[idx] * C_ssm[idx];
    g_AbarP[idx] = expf(dA * (float)TC);
}

// ---------------------------------------------------------------------------
// Head precompute: sw = scale*w per channel, plus 4 reduced constants
// ---------------------------------------------------------------------------
__global__ void head_prep_kernel(const float* __restrict__ s_f0, const float* __restrict__ bi_f0,
                                 const float* __restrict__ w_f0,
                                 const float* __restrict__ s_en, const float* __restrict__ bi_en,
                                 const float* __restrict__ w_en) {
    __shared__ float red[4][16];
    int d = threadIdx.x;                 // 512 threads
    float wf = w_f0[d], we = w_en[d];
    float v0 = s_f0[d] * wf;             // SW f0 term
    float v1 = bi_f0[d] * wf;            // BW f0 term
    float v2 = s_en[d] * we;
    float v3 = bi_en[d] * we;
    g_swf0[d] = v0; g_swen[d] = v2;

    float v[4] = {v0, v1, v2, v3};
    int lane = d & 31, w = d >> 5;
#pragma unroll
    for (int j = 0; j < 4; j++) {
        float x = v[j];
#pragma unroll
        for (int o = 16; o > 0; o >>= 1) x += __shfl_xor_sync(0xffffffffu, x, o);
        if (lane == 0) red[j][w] = x;
    }
    __syncthreads();
    if (d < 4) {
        float s = 0.0f;
#pragma unroll
        for (int k = 0; k < 16; k++) s += red[d][k];
        g_hc[d] = s;
    }
}

// ---------------------------------------------------------------------------
// TF32 tensor-core GEMM: g_ht[b][d][t] = (X@W)[row=(b,t)][d] + bias[d] + freq[t][d]
// M=8192, N=512, K=512.  BM=128, BN=64, BK=16; 256 threads, 8 warps (4m x 2n).
// Epilogue transposes through smem so global stores are along t.
// ---------------------------------------------------------------------------
#define AST 20     // As row stride (words)
#define BST 20     // Bs row stride (words)

__global__ __launch_bounds__(256)
void gemm_tf32_kernel(const float* __restrict__ X, const float* __restrict__ W,
                      const float* __restrict__ bias, const float* __restrict__ freq) {
    __shared__ __align__(16) unsigned char smem_raw[34048];
    uint32_t* As = (uint32_t*)smem_raw;                 // [2][128*20]
    uint32_t* Bs = (uint32_t*)(smem_raw + 20480);       // [2][64*20]

    int tid = threadIdx.x;
    int lane = tid & 31, wid = tid >> 5;
    int warp_m = wid >> 1, warp_n = wid & 1;
    int rowBase = blockIdx.y * 128;
    int colBase = blockIdx.x * 64;

    float acc[2][4][4];
#pragma unroll
    for (int i = 0; i < 2; i++)
#pragma unroll
        for (int j = 0; j < 4; j++)
#pragma unroll
            for (int k = 0; k < 4; k++) acc[i][j][k] = 0.0f;

    // ldmatrix per-lane addressing
    int a_row = (lane & 7) + ((lane >> 3) & 1) * 8;
    int a_colw = (lane >> 4) * 4;
    const uint32_t* aPtr = As + (warp_m * 32 + a_row) * AST + a_colw;
    int b_row = (lane & 7) + ((lane >> 4) << 3);
    int b_colw = ((lane >> 3) & 1) * 4;
    const uint32_t* bPtr = Bs + (warp_n * 32 + b_row) * BST + b_colw;

    // gmem->smem mapping
    int arow = tid >> 2;                // 0..63 (+64)
    int acol = (tid & 3) << 2;          // word 0,4,8,12
    int bn   = tid & 63;                // local n
    int bk0  = (tid >> 6) << 2;         // k word 0,4,8,12

    const float* Xp = X + (size_t)rowBase * Ee;
    const float* Wp = W + colBase;

    // prologue: tile kt=0 -> buf 0
    {
        float4 va0 = *(const float4*)(Xp + (size_t)arow * Ee + acol);
        float4 va1 = *(const float4*)(Xp + (size_t)(arow + 64) * Ee + acol);
        uint4 ua0 = make_uint4(f2tf(va0.x), f2tf(va0.y), f2tf(va0.z), f2tf(va0.w));
        uint4 ua1 = make_uint4(f2tf(va1.x), f2tf(va1.y), f2tf(va1.z), f2tf(va1.w));
        *(uint4*)&As[arow * AST + acol] = ua0;
        *(uint4*)&As[(arow + 64) * AST + acol] = ua1;
        float b0 = Wp[(size_t)(bk0 + 0) * Dd + bn];
        float b1 = Wp[(size_t)(bk0 + 1) * Dd + bn];
        float b2 = Wp[(size_t)(bk0 + 2) * Dd + bn];
        float b3 = Wp[(size_t)(bk0 + 3) * Dd + bn];
        *(uint4*)&Bs[bn * BST + bk0] = make_uint4(f2tf(b0), f2tf(b1), f2tf(b2), f2tf(b3));
    }
    __syncthreads();

    int buf = 0;
    for (int kt = 16; kt < Ee; kt += 16) {
        // prefetch next tile to regs
        float4 va0 = *(const float4*)(Xp + (size_t)arow * Ee + kt + acol);
        float4 va1 = *(const float4*)(Xp + (size_t)(arow + 64) * Ee + kt + acol);
        float pb0 = Wp[(size_t)(kt + bk0 + 0) * Dd + bn];
        float pb1 = Wp[(size_t)(kt + bk0 + 1) * Dd + bn];
        float pb2 = Wp[(size_t)(kt + bk0 + 2) * Dd + bn];
        float pb3 = Wp[(size_t)(kt + bk0 + 3) * Dd + bn];

        // compute current buffer
        const uint32_t* aB = aPtr + buf * 2560;
        const uint32_t* bB = bPtr + buf * 1280;
#pragma unroll
        for (int k8 = 0; k8 < 2; k8++) {
            uint32_t a[2][4], bb[2][4];
            ldsm4(a[0][0], a[0][1], a[0][2], a[0][3], aB + k8 * 8);
            ldsm4(a[1][0], a[1][1], a[1][2], a[1][3], aB + 320 + k8 * 8);
            ldsm4(bb[0][0], bb[0][1], bb[0][2], bb[0][3], bB + k8 * 8);
            ldsm4(bb[1][0], bb[1][1], bb[1][2], bb[1][3], bB + 320 + k8 * 8);
#pragma unroll
            for (int mi = 0; mi < 2; mi++) {
                mma_tf32(acc[mi][0], a[mi], bb[0][0], bb[0][1]);
                mma_tf32(acc[mi][1], a[mi], bb[0][2], bb[0][3]);
                mma_tf32(acc[mi][2], a[mi], bb[1][0], bb[1][1]);
                mma_tf32(acc[mi][3], a[mi], bb[1][2], bb[1][3]);
            }
        }

        // store prefetched tile
        int nb = buf ^ 1;
        uint4 ua0 = make_uint4(f2tf(va0.x), f2tf(va0.y), f2tf(va0.z), f2tf(va0.w));
        uint4 ua1 = make_uint4(f2tf(va1.x), f2tf(va1.y), f2tf(va1.z), f2tf(va1.w));
        *(uint4*)&As[nb * 2560 + arow * AST + acol] = ua0;
        *(uint4*)&As[nb * 2560 + (arow + 64) * AST + acol] = ua1;
        *(uint4*)&Bs[nb * 1280 + bn * BST + bk0] =
            make_uint4(f2tf(pb0), f2tf(pb1), f2tf(pb2), f2tf(pb3));
        __syncthreads();
        buf = nb;
    }

    // last tile
    {
        const uint32_t* aB = aPtr + buf * 2560;
        const uint32_t* bB = bPtr + buf * 1280;
#pragma unroll
        for (int k8 = 0; k8 < 2; k8++) {
            uint32_t a[2][4], bb[2][4];
            ldsm4(a[0][0], a[0][1], a[0][2], a[0][3], aB + k8 * 8);
            ldsm4(a[1][0], a[1][1], a[1][2], a[1][3], aB + 320 + k8 * 8);
            ldsm4(bb[0][0], bb[0][1], bb[0][2], bb[0][3], bB + k8 * 8);
            ldsm4(bb[1][0], bb[1][1], bb[1][2], bb[1][3], bB + 320 + k8 * 8);
#pragma unroll
            for (int mi = 0; mi < 2; mi++) {
                mma_tf32(acc[mi][0], a[mi], bb[0][0], bb[0][1]);
                mma_tf32(acc[mi][1], a[mi], bb[0][2], bb[0][3]);
                mma_tf32(acc[mi][2], a[mi], bb[1][0], bb[1][1]);
                mma_tf32(acc[mi][3], a[mi], bb[1][2], bb[1][3]);
            }
        }
    }
    __syncthreads();

    // Epilogue: acc (+bias+freq) -> smem transpose -> g_ht[b][d][t]
    float* SE = (float*)smem_raw;        // [64][132]
    int g = lane >> 2, tk = lane & 3;
#pragma unroll
    for (int mi = 0; mi < 2; mi++) {
#pragma unroll
        for (int ni = 0; ni < 4; ni++) {
            int rl = warp_m * 32 + mi * 16 + g;
            int cl = warp_n * 32 + ni * 8 + 2 * tk;
            int t0g = (rowBase + rl) & (Tt - 1);
            int t1g = (rowBase + rl + 8) & (Tt - 1);
            int c0 = colBase + cl, c1 = c0 + 1;
            SE[cl * 132 + rl]           = acc[mi][ni][0] + bias[c0] + freq[(size_t)t0g * Dd + c0];
            SE[(cl + 1) * 132 + rl]     = acc[mi][ni][1] + bias[c1] + freq[(size_t)t0g * Dd + c1];
            SE[cl * 132 + rl + 8]       = acc[mi][ni][2] + bias[c0] + freq[(size_t)t1g * Dd + c0];
            SE[(cl + 1) * 132 + rl + 8] = acc[mi][ni][3] + bias[c1] + freq[(size_t)t1g * Dd + c1];
        }
    }
    __syncthreads();

    int b = rowBase >> 11;
    int t0 = rowBase & (Tt - 1);
#pragma unroll
    for (int i = 0; i < 8; i++) {
        int idx = i * 256 + tid;         // 0..2047
        int dr = idx >> 5;               // 0..63
        int w  = idx & 31;               // float4 within t-row
        float4 v = *(float4*)&SE[dr * 132 + w * 4];
        *(float4*)&g_ht[((size_t)(b * Dd) + colBase + dr) * Tt + t0 + w * 4] = v;
    }
}

// ---------------------------------------------------------------------------
// Fused 4-layer S4 stack on transposed layout. One block = (b, 4 channels).
// Block 256 threads: thread (c 0..63, dl 0..3). Grid = B*(D/4) = 512.
// ---------------------------------------------------------------------------
__global__ __launch_bounds__(256)
void s4_stack_kernel(const float* __restrict__ D_skip) {
    __shared__ float sx[NCH * SXS];     // 16.9 KB

    int tid  = threadIdx.x;
    int dl   = tid & (DBLK - 1);
    int c    = tid >> 2;
    int b    = blockIdx.x >> 7;
    int dblk = blockIdx.x & 127;
    int d    = dblk * DBLK + dl;

    int seg = tid & 3;
    int dn  = tid >> 2;
    int dl2 = dn >> 4, n2 = dn & 15;

    // Contiguous per-thread u (vectorized)
    float4 uv[8];
    float* hp = g_ht + ((size_t)(b * Dd) + d) * Tt + c * TC;
#pragma unroll
    for (int j = 0; j < 8; j++) uv[j] = ((float4*)hp)[j];
    float* u = (float*)uv;

    for (int l = 0; l < Ll; l++) {
        ull a2[8];
        {
            const float4* ap4 = (const float4*)(g_Abar + (size_t)l * DN + d * Nn);
#pragma unroll
            for (int q = 0; q < 4; q++) {
                float4 v = ap4[q];
                a2[2*q]   = pack2(v.x, v.y);
                a2[2*q+1] = pack2(v.z, v.w);
            }
        }

        // Phase 1: chunk scan from zero (z-form)
        ull z2[8];
#pragma unroll
        for (int q = 0; q < 8; q++) z2[q] = 0ull;
#pragma unroll
        for (int i = 0; i < TC; i++) {
            ull u2 = pack2(u[i], u[i]);
#pragma unroll
            for (int q = 0; q < 8; q++)
                z2[q] = fma2(a2[q], z2[q], u2);
        }
        {
            ull* so = (ull*)(sx + c * SXS + dl * Nn);
#pragma unroll
            for (int q = 0; q < 8; q++) so[q] = z2[q];
        }
        __syncthreads();

        // Phase 2: shuffle scan across 64 chunks
        {
            float ap = g_AbarP[(size_t)l * DN + (dblk * DBLK + dl2) * Nn + n2];
            float f[16];
#pragma unroll
            for (int j = 0; j < 16; j++)
                f[j] = sx[(seg * 16 + j) * SXS + dn];

            float F = 0.0f;
#pragma unroll
            for (int j = 0; j < 16; j++) F = fmaf(ap, F, f[j]);

            float p2 = ap * ap, p4 = p2 * p2, p8 = p4 * p4;
            float m  = p8 * p8;

            float Fp = __shfl_up_sync(0xffffffffu, F, 1, 4);
            float mp = __shfl_up_sync(0xffffffffu, m, 1, 4);
            if (seg >= 1) { F = fmaf(m, Fp, F); m *= mp; }
            Fp = __shfl_up_sync(0xffffffffu, F, 2, 4);
            mp = __shfl_up_sync(0xffffffffu, m, 2, 4);
            if (seg >= 2) { F = fmaf(m, Fp, F); m *= mp; }

            float carry = __shfl_up_sync(0xffffffffu, F, 1, 4);
            if (seg == 0) carry = 0.0f;

            float xs = carry;
#pragma unroll
            for (int j = 0; j < 16; j++) {
                sx[(seg * 16 + j) * SXS + dn] = xs;
                xs = fmaf(ap, xs, f[j]);
            }
        }
        __syncthreads();

        // Phase 3: re-scan + fused epilogue
        ull cb2[8];
        {
            const float4* cp4 = (const float4*)(g_CB + (size_t)l * DN + d * Nn);
#pragma unroll
            for (int q = 0; q < 4; q++) {
                float4 v = cp4[q];
                cb2[2*q]   = pack2(v.x, v.y);
                cb2[2*q+1] = pack2(v.z, v.w);
            }
        }
        float dsk = D_skip[l * Dd + d];

        {
            const ull* si = (const ull*)(sx + c * SXS + dl * Nn);
#pragma unroll
            for (int q = 0; q < 8; q++) z2[q] = si[q];
        }

#pragma unroll
        for (int i = 0; i < TC; i++) {
            float uu = u[i];
            ull u2 = pack2(uu, uu);
            ull y2 = 0ull;
#pragma unroll
            for (int q = 0; q < 8; q++) {
                z2[q] = fma2(a2[q], z2[q], u2);
                y2 = fma2(z2[q], cb2[q], y2);
            }
            float ylo, yhi; unpack2(y2, ylo, yhi);
            float y = ylo + yhi;
            y = fmaf(dsk, uu, y);
            float yy = y * y;
            float inner2 = 1.5957691216057308f * (y + 0.044715f * y * yy);
            float e = __expf(-inner2);
            float g = __fdividef(y, 1.0f + e);
            u[i] = uu + g;
        }
    }

#pragma unroll
    for (int j = 0; j < 8; j++) ((float4*)hp)[j] = uv[j];
}

// ---------------------------------------------------------------------------
// Head on transposed layout, single pass.
// Block 256 thr: tt = tid&31 (t), oct = tid>>5 (64 d each). Grid = 8192/32.
// ---------------------------------------------------------------------------
__global__ __launch_bounds__(256)
void head_kernel(const float* __restrict__ b_f0, const float* __restrict__ b_en,
                 float* __restrict__ out) {
    __shared__ float sh[8][4][32];
    int tid = threadIdx.x;
    int tt = tid & 31, oct = tid >> 5;
    int rowBase = blockIdx.x * 32;
    int b = rowBase >> 11, t0 = rowBase & (Tt - 1);

    const float* hp = g_ht + ((size_t)(b * Dd) + oct * 64) * Tt + t0 + tt;
    const float* swf = g_swf0 + oct * 64;
    const float* swe = g_swen + oct * 64;

    float s1 = 0.0f, s2 = 0.0f, sf = 0.0f, se = 0.0f;
#pragma unroll 8
    for (int dd = 0; dd < 64; dd++) {
        float v = hp[(size_t)dd * Tt];
        s1 += v;
        s2 = fmaf(v, v, s2);
        sf = fmaf(v, __ldg(swf + dd), sf);
        se = fmaf(v, __ldg(swe + dd), se);
    }
    sh[oct][0][tt] = s1; sh[oct][1][tt] = s2;
    sh[oct][2][tt] = sf; sh[oct][3][tt] = se;
    __syncthreads();

    if (tid < 32) {
        float a0 = 0.0f, a1 = 0.0f, a2 = 0.0f, a3 = 0.0f;
#pragma unroll
        for (int o = 0; o < 8; o++) {
            a0 += sh[o][0][tt]; a1 += sh[o][1][tt];
            a2 += sh[o][2][tt]; a3 += sh[o][3][tt];
        }
        float mu = a0 * (1.0f / Dd);
        float var = a1 * (1.0f / Dd) - mu * mu;
        float rstd = rsqrtf(var + 1e-5f);
        out[rowBase + tt]                   = rstd * (a2 - mu * g_hc[0]) + g_hc[1] + b_f0[0];
        out[(size_t)Bb * Tt + rowBase + tt] = rstd * (a3 - mu * g_hc[2]) + g_hc[3] + b_en[0];
    }
}

// ---------------------------------------------------------------------------
extern "C" void kernel_launch(void* const* d_in, const int* in_sizes, int n_in,
                              void* d_out, int out_size) {
    const float* text_emb = (const float*)d_in[0];
    const float* W_in     = (const float*)d_in[1];
    const float* b_in     = (const float*)d_in[2];
    const float* freq_pe  = (const float*)d_in[3];
    const float* A_log    = (const float*)d_in[4];
    const float* B_ssm    = (const float*)d_in[5];
    const float* C_ssm    = (const float*)d_in[6];
    const float* log_dt   = (const float*)d_in[7];
    const float* D_skip   = (const float*)d_in[8];
    const float* ln_f0_s  = (const float*)d_in[9];
    const float* ln_f0_b  = (const float*)d_in[10];
    const float* W_f0     = (const float*)d_in[11];
    const float* b_f0     = (const float*)d_in[12];
    const float* ln_en_s  = (const float*)d_in[13];
    const float* ln_en_b  = (const float*)d_in[14];
    const float* W_en     = (const float*)d_in[15];
    const float* b_en     = (const float*)d_in[16];
    float* out = (float*)d_out;

    precompute_kernel<<<(Ll * DN + 255) / 256, 256>>>(A_log, B_ssm, C_ssm, log_dt);
    head_prep_kernel<<<1, Dd>>>(ln_f0_s, ln_f0_b, W_f0, ln_en_s, ln_en_b, W_en);

    dim3 ggrid(Dd / 64, (Bb * Tt) / 128);
    gemm_tf32_kernel<<<ggrid, 256>>>(text_emb, W_in, b_in, freq_pe);

    s4_stack_kernel<<<Bb * (Dd / DBLK), 256>>>(D_skip);

    head_kernel<<<(Bb * Tt) / 32, 256>>>(b_f0, b_en, out);
}

// round 6
// speedup vs baseline: 2.9683x; 1.0198x over previous
#include <cuda_runtime.h>
#include <math.h>
#include <stdint.h>

// Problem constants
#define Bb   4
#define Tt   2048
#define Ee   512
#define Dd   512
#define Nn   16
#define Ll   4
#define TC   32              // chunk length (time steps per thread)
#define NCH  (Tt / TC)       // 64 chunks
#define DN   (Dd * Nn)       // 8192
#define DBLK 2               // d-channels per block in fused scan
#define SXS  34              // padded smem row stride (floats, even for ull)

typedef unsigned long long ull;

__device__ __forceinline__ ull pack2(float lo, float hi) {
    ull r; asm("mov.b64 %0, {%1,%2};" : "=l"(r) : "f"(lo), "f"(hi)); return r;
}
__device__ __forceinline__ void unpack2(ull v, float& lo, float& hi) {
    asm("mov.b64 {%0,%1}, %2;" : "=f"(lo), "=f"(hi) : "l"(v));
}
__device__ __forceinline__ ull fma2(ull a, ull b, ull c) {
    ull d; asm("fma.rn.f32x2 %0, %1, %2, %3;" : "=l"(d) : "l"(a), "l"(b), "l"(c));
    return d;
}
__device__ __forceinline__ uint32_t f2tf(float f) {
    uint32_t u; asm("cvt.rna.tf32.f32 %0, %1;" : "=r"(u) : "f"(f)); return u;
}
__device__ __forceinline__ void ldsm4(uint32_t& r0, uint32_t& r1, uint32_t& r2,
                                      uint32_t& r3, const uint32_t* p) {
    uint32_t a = (uint32_t)__cvta_generic_to_shared(p);
    asm volatile("ldmatrix.sync.aligned.m8n8.x4.shared.b16 {%0,%1,%2,%3}, [%4];"
                 : "=r"(r0), "=r"(r1), "=r"(r2), "=r"(r3) : "r"(a));
}
__device__ __forceinline__ void mma_tf32(float* c, const uint32_t* a,
                                         uint32_t b0, uint32_t b1) {
    asm volatile("mma.sync.aligned.m16n8k8.row.col.f32.tf32.tf32.f32 "
                 "{%0,%1,%2,%3}, {%4,%5,%6,%7}, {%8,%9}, {%0,%1,%2,%3};"
                 : "+f"(c[0]), "+f"(c[1]), "+f"(c[2]), "+f"(c[3])
                 : "r"(a[0]), "r"(a[1]), "r"(a[2]), "r"(a[3]), "r"(b0), "r"(b1));
}

// Scratch (static device globals; no runtime allocation)
__device__ float g_ht[(size_t)Bb * Dd * Tt];       // residual stream, TRANSPOSED [b][d][t]
__device__ float g_Abar [Ll * DN];
__device__ float g_CB   [Ll * DN];                 // C * Bbar
__device__ float g_AbarP[Ll * DN];                 // Abar^TC
__device__ float g_swf0[Dd], g_swen[Dd];           // scale*weight per head
__device__ float g_hc[4];                          // SWf0, BWf0, SWen, BWen

// ---------------------------------------------------------------------------
// Precompute per-layer SSM constants
// ---------------------------------------------------------------------------
__global__ void precompute_kernel(const float* __restrict__ A_log,
                                  const float* __restrict__ B_ssm,
                                  const float* __restrict__ C_ssm,
                                  const float* __restrict__ log_dt) {
    int idx = blockIdx.x * blockDim.x + threadIdx.x;
    if (idx >= Ll * DN) return;
    int l  = idx / DN;
    int dn = idx % DN;
    int d  = dn / Nn;
    float dt = expf(log_dt[l * Dd + d]);
    float A  = -expf(A_log[idx]);
    float dA = dt * A;
    float ab = expf(dA);
    g_Abar [idx] = ab;
    g_CB   [idx] = (ab - 1.0f) / A * B_ssm[idx] * C_ssm[idx];
    g_AbarP[idx] = expf(dA * (float)TC);
}

// ---------------------------------------------------------------------------
// Head precompute
// ---------------------------------------------------------------------------
__global__ void head_prep_kernel(const float* __restrict__ s_f0, const float* __restrict__ bi_f0,
                                 const float* __restrict__ w_f0,
                                 const float* __restrict__ s_en, const float* __restrict__ bi_en,
                                 const float* __restrict__ w_en) {
    __shared__ float red[4][16];
    int d = threadIdx.x;                 // 512 threads
    float wf = w_f0[d], we = w_en[d];
    float v0 = s_f0[d] * wf;
    float v1 = bi_f0[d] * wf;
    float v2 = s_en[d] * we;
    float v3 = bi_en[d] * we;
    g_swf0[d] = v0; g_swen[d] = v2;

    float v[4] = {v0, v1, v2, v3};
    int lane = d & 31, w = d >> 5;
#pragma unroll
    for (int j = 0; j < 4; j++) {
        float x = v[j];
#pragma unroll
        for (int o = 16; o > 0; o >>= 1) x += __shfl_xor_sync(0xffffffffu, x, o);
        if (lane == 0) red[j][w] = x;
    }
    __syncthreads();
    if (d < 4) {
        float s = 0.0f;
#pragma unroll
        for (int k = 0; k < 16; k++) s += red[d][k];
        g_hc[d] = s;
    }
}

// ---------------------------------------------------------------------------
// TF32 tensor-core GEMM: g_ht[b][d][t] = (X@W)[row=(b,t)][d] + bias[d] + freq[t][d]
// ---------------------------------------------------------------------------
#define AST 20
#define BST 20

__global__ __launch_bounds__(256)
void gemm_tf32_kernel(const float* __restrict__ X, const float* __restrict__ W,
                      const float* __restrict__ bias, const float* __restrict__ freq) {
    __shared__ __align__(16) unsigned char smem_raw[34048];
    uint32_t* As = (uint32_t*)smem_raw;
    uint32_t* Bs = (uint32_t*)(smem_raw + 20480);

    int tid = threadIdx.x;
    int lane = tid & 31, wid = tid >> 5;
    int warp_m = wid >> 1, warp_n = wid & 1;
    int rowBase = blockIdx.y * 128;
    int colBase = blockIdx.x * 64;

    float acc[2][4][4];
#pragma unroll
    for (int i = 0; i < 2; i++)
#pragma unroll
        for (int j = 0; j < 4; j++)
#pragma unroll
            for (int k = 0; k < 4; k++) acc[i][j][k] = 0.0f;

    int a_row = (lane & 7) + ((lane >> 3) & 1) * 8;
    int a_colw = (lane >> 4) * 4;
    const uint32_t* aPtr = As + (warp_m * 32 + a_row) * AST + a_colw;
    int b_row = (lane & 7) + ((lane >> 4) << 3);
    int b_colw = ((lane >> 3) & 1) * 4;
    const uint32_t* bPtr = Bs + (warp_n * 32 + b_row) * BST + b_colw;

    int arow = tid >> 2;
    int acol = (tid & 3) << 2;
    int bn   = tid & 63;
    int bk0  = (tid >> 6) << 2;

    const float* Xp = X + (size_t)rowBase * Ee;
    const float* Wp = W + colBase;

    {
        float4 va0 = *(const float4*)(Xp + (size_t)arow * Ee + acol);
        float4 va1 = *(const float4*)(Xp + (size_t)(arow + 64) * Ee + acol);
        uint4 ua0 = make_uint4(f2tf(va0.x), f2tf(va0.y), f2tf(va0.z), f2tf(va0.w));
        uint4 ua1 = make_uint4(f2tf(va1.x), f2tf(va1.y), f2tf(va1.z), f2tf(va1.w));
        *(uint4*)&As[arow * AST + acol] = ua0;
        *(uint4*)&As[(arow + 64) * AST + acol] = ua1;
        float b0 = Wp[(size_t)(bk0 + 0) * Dd + bn];
        float b1 = Wp[(size_t)(bk0 + 1) * Dd + bn];
        float b2 = Wp[(size_t)(bk0 + 2) * Dd + bn];
        float b3 = Wp[(size_t)(bk0 + 3) * Dd + bn];
        *(uint4*)&Bs[bn * BST + bk0] = make_uint4(f2tf(b0), f2tf(b1), f2tf(b2), f2tf(b3));
    }
    __syncthreads();

    int buf = 0;
    for (int kt = 16; kt < Ee; kt += 16) {
        float4 va0 = *(const float4*)(Xp + (size_t)arow * Ee + kt + acol);
        float4 va1 = *(const float4*)(Xp + (size_t)(arow + 64) * Ee + kt + acol);
        float pb0 = Wp[(size_t)(kt + bk0 + 0) * Dd + bn];
        float pb1 = Wp[(size_t)(kt + bk0 + 1) * Dd + bn];
        float pb2 = Wp[(size_t)(kt + bk0 + 2) * Dd + bn];
        float pb3 = Wp[(size_t)(kt + bk0 + 3) * Dd + bn];

        const uint32_t* aB = aPtr + buf * 2560;
        const uint32_t* bB = bPtr + buf * 1280;
#pragma unroll
        for (int k8 = 0; k8 < 2; k8++) {
            uint32_t a[2][4], bb[2][4];
            ldsm4(a[0][0], a[0][1], a[0][2], a[0][3], aB + k8 * 8);
            ldsm4(a[1][0], a[1][1], a[1][2], a[1][3], aB + 320 + k8 * 8);
            ldsm4(bb[0][0], bb[0][1], bb[0][2], bb[0][3], bB + k8 * 8);
            ldsm4(bb[1][0], bb[1][1], bb[1][2], bb[1][3], bB + 320 + k8 * 8);
#pragma unroll
            for (int mi = 0; mi < 2; mi++) {
                mma_tf32(acc[mi][0], a[mi], bb[0][0], bb[0][1]);
                mma_tf32(acc[mi][1], a[mi], bb[0][2], bb[0][3]);
                mma_tf32(acc[mi][2], a[mi], bb[1][0], bb[1][1]);
                mma_tf32(acc[mi][3], a[mi], bb[1][2], bb[1][3]);
            }
        }

        int nb = buf ^ 1;
        uint4 ua0 = make_uint4(f2tf(va0.x), f2tf(va0.y), f2tf(va0.z), f2tf(va0.w));
        uint4 ua1 = make_uint4(f2tf(va1.x), f2tf(va1.y), f2tf(va1.z), f2tf(va1.w));
        *(uint4*)&As[nb * 2560 + arow * AST + acol] = ua0;
        *(uint4*)&As[nb * 2560 + (arow + 64) * AST + acol] = ua1;
        *(uint4*)&Bs[nb * 1280 + bn * BST + bk0] =
            make_uint4(f2tf(pb0), f2tf(pb1), f2tf(pb2), f2tf(pb3));
        __syncthreads();
        buf = nb;
    }

    {
        const uint32_t* aB = aPtr + buf * 2560;
        const uint32_t* bB = bPtr + buf * 1280;
#pragma unroll
        for (int k8 = 0; k8 < 2; k8++) {
            uint32_t a[2][4], bb[2][4];
            ldsm4(a[0][0], a[0][1], a[0][2], a[0][3], aB + k8 * 8);
            ldsm4(a[1][0], a[1][1], a[1][2], a[1][3], aB + 320 + k8 * 8);
            ldsm4(bb[0][0], bb[0][1], bb[0][2], bb[0][3], bB + k8 * 8);
            ldsm4(bb[1][0], bb[1][1], bb[1][2], bb[1][3], bB + 320 + k8 * 8);
#pragma unroll
            for (int mi = 0; mi < 2; mi++) {
                mma_tf32(acc[mi][0], a[mi], bb[0][0], bb[0][1]);
                mma_tf32(acc[mi][1], a[mi], bb[0][2], bb[0][3]);
                mma_tf32(acc[mi][2], a[mi], bb[1][0], bb[1][1]);
                mma_tf32(acc[mi][3], a[mi], bb[1][2], bb[1][3]);
            }
        }
    }
    __syncthreads();

    float* SE = (float*)smem_raw;        // [64][132]
    int g = lane >> 2, tk = lane & 3;
#pragma unroll
    for (int mi = 0; mi < 2; mi++) {
#pragma unroll
        for (int ni = 0; ni < 4; ni++) {
            int rl = warp_m * 32 + mi * 16 + g;
            int cl = warp_n * 32 + ni * 8 + 2 * tk;
            int t0g = (rowBase + rl) & (Tt - 1);
            int t1g = (rowBase + rl + 8) & (Tt - 1);
            int c0 = colBase + cl, c1 = c0 + 1;
            SE[cl * 132 + rl]           = acc[mi][ni][0] + bias[c0] + freq[(size_t)t0g * Dd + c0];
            SE[(cl + 1) * 132 + rl]     = acc[mi][ni][1] + bias[c1] + freq[(size_t)t0g * Dd + c1];
            SE[cl * 132 + rl + 8]       = acc[mi][ni][2] + bias[c0] + freq[(size_t)t1g * Dd + c0];
            SE[(cl + 1) * 132 + rl + 8] = acc[mi][ni][3] + bias[c1] + freq[(size_t)t1g * Dd + c1];
        }
    }
    __syncthreads();

    int b = rowBase >> 11;
    int t0 = rowBase & (Tt - 1);
#pragma unroll
    for (int i = 0; i < 8; i++) {
        int idx = i * 256 + tid;
        int dr = idx >> 5;
        int w  = idx & 31;
        float4 v = *(float4*)&SE[dr * 132 + w * 4];
        *(float4*)&g_ht[((size_t)(b * Dd) + colBase + dr) * Tt + t0 + w * 4] = v;
    }
}

// ---------------------------------------------------------------------------
// Fused 4-layer S4 stack, u in swizzled smem. Block = 128 thr (c 0..63, dl 0..1).
// Grid = B*(D/2) = 1024 blocks. Low regs -> 6 blocks/SM.
// ---------------------------------------------------------------------------
__global__ __launch_bounds__(128, 6)
void s4_stack_kernel(const float* __restrict__ D_skip) {
    __shared__ float sx[NCH * SXS];     // 64*34*4 = 8.7 KB
    __shared__ float us[DBLK * Tt];     // 2*2048*4 = 16 KB

    int tid  = threadIdx.x;
    int dl   = tid & 1;
    int c    = tid >> 1;
    int b    = blockIdx.x >> 8;
    int dblk = blockIdx.x & 255;
    int d    = dblk * DBLK + dl;
    int rot  = tid & 31;
    int chanbase = dl * Tt + c * TC;

    // phase-2 mapping
    int seg = tid & 3;                  // 0..3
    int dn  = tid >> 2;                 // 0..31
    int dl2 = dn >> 4, n2 = dn & 15;

    // Cooperative load: 2 channels x 2048 floats -> swizzled us
    const float4* gb4 = (const float4*)(g_ht + ((size_t)(b * Dd) + dblk * DBLK) * Tt);
#pragma unroll
    for (int j = 0; j < 8; j++) {
        int p = j * 128 + tid;          // 0..1023 float4
        float4 v = gb4[p];
        int ch = p >> 9;
        int t  = (p & 511) << 2;
        int base = ch * Tt + (t & ~31);
        int rr = (((t >> 5) << 1) + ch) & 31;
        int i0 = t & 31;
        us[base + ((i0 + 0) ^ rr)] = v.x;
        us[base + ((i0 + 1) ^ rr)] = v.y;
        us[base + ((i0 + 2) ^ rr)] = v.z;
        us[base + ((i0 + 3) ^ rr)] = v.w;
    }
    __syncthreads();

    for (int l = 0; l < Ll; l++) {
        ull a2[8];
        {
            const float4* ap4 = (const float4*)(g_Abar + (size_t)l * DN + d * Nn);
#pragma unroll
            for (int q = 0; q < 4; q++) {
                float4 v = ap4[q];
                a2[2*q]   = pack2(v.x, v.y);
                a2[2*q+1] = pack2(v.z, v.w);
            }
        }

        // Phase 1: chunk scan from zero (z-form)
        ull z2[8];
#pragma unroll
        for (int q = 0; q < 8; q++) z2[q] = 0ull;
#pragma unroll
        for (int i = 0; i < TC; i++) {
            float uu = us[chanbase + (i ^ rot)];
            ull u2 = pack2(uu, uu);
#pragma unroll
            for (int q = 0; q < 8; q++)
                z2[q] = fma2(a2[q], z2[q], u2);
        }
        {
            ull* so = (ull*)(sx + c * SXS + dl * Nn);
#pragma unroll
            for (int q = 0; q < 8; q++) so[q] = z2[q];
        }
        __syncthreads();

        // Phase 2: shuffle scan across 64 chunks (4 segments of 16)
        {
            float ap = g_AbarP[(size_t)l * DN + (dblk * DBLK + dl2) * Nn + n2];
            float f[16];
#pragma unroll
            for (int j = 0; j < 16; j++)
                f[j] = sx[(seg * 16 + j) * SXS + dn];

            float F = 0.0f;
#pragma unroll
            for (int j = 0; j < 16; j++) F = fmaf(ap, F, f[j]);

            float p2 = ap * ap, p4 = p2 * p2, p8 = p4 * p4;
            float m  = p8 * p8;             // ap^16

            float Fp = __shfl_up_sync(0xffffffffu, F, 1, 4);
            float mp = __shfl_up_sync(0xffffffffu, m, 1, 4);
            if (seg >= 1) { F = fmaf(m, Fp, F); m *= mp; }
            Fp = __shfl_up_sync(0xffffffffu, F, 2, 4);
            mp = __shfl_up_sync(0xffffffffu, m, 2, 4);
            if (seg >= 2) { F = fmaf(m, Fp, F); m *= mp; }

            float carry = __shfl_up_sync(0xffffffffu, F, 1, 4);
            if (seg == 0) carry = 0.0f;

            float xs = carry;
#pragma unroll
            for (int j = 0; j < 16; j++) {
                sx[(seg * 16 + j) * SXS + dn] = xs;
                xs = fmaf(ap, xs, f[j]);
            }
        }
        __syncthreads();

        // Phase 3: re-scan + fused epilogue, u updated in smem
        ull cb2[8];
        {
            const float4* cp4 = (const float4*)(g_CB + (size_t)l * DN + d * Nn);
#pragma unroll
            for (int q = 0; q < 4; q++) {
                float4 v = cp4[q];
                cb2[2*q]   = pack2(v.x, v.y);
                cb2[2*q+1] = pack2(v.z, v.w);
            }
        }
        float dsk = D_skip[l * Dd + d];

        {
            const ull* si = (const ull*)(sx + c * SXS + dl * Nn);
#pragma unroll
            for (int q = 0; q < 8; q++) z2[q] = si[q];
        }

#pragma unroll
        for (int i = 0; i < TC; i++) {
            float uu = us[chanbase + (i ^ rot)];
            ull u2 = pack2(uu, uu);
            ull y2 = 0ull;
#pragma unroll
            for (int q = 0; q < 8; q++) {
                z2[q] = fma2(a2[q], z2[q], u2);
                y2 = fma2(z2[q], cb2[q], y2);
            }
            float ylo, yhi; unpack2(y2, ylo, yhi);
            float y = ylo + yhi;
            y = fmaf(dsk, uu, y);
            float yy = y * y;
            float inner2 = 1.5957691216057308f * (y + 0.044715f * y * yy);
            float e = __expf(-inner2);
            float g = __fdividef(y, 1.0f + e);
            us[chanbase + (i ^ rot)] = uu + g;
        }
        // No sync needed before next layer's phase 1: each thread re-reads
        // only the us/sx slots it itself wrote.
    }
    __syncthreads();

    // Cooperative writeback (reverse swizzle)
    float4* gb4o = (float4*)(g_ht + ((size_t)(b * Dd) + dblk * DBLK) * Tt);
#pragma unroll
    for (int j = 0; j < 8; j++) {
        int p = j * 128 + tid;
        int ch = p >> 9;
        int t  = (p & 511) << 2;
        int base = ch * Tt + (t & ~31);
        int rr = (((t >> 5) << 1) + ch) & 31;
        int i0 = t & 31;
        float4 v;
        v.x = us[base + ((i0 + 0) ^ rr)];
        v.y = us[base + ((i0 + 1) ^ rr)];
        v.z = us[base + ((i0 + 2) ^ rr)];
        v.w = us[base + ((i0 + 3) ^ rr)];
        gb4o[p] = v;
    }
}

// ---------------------------------------------------------------------------
// Head on transposed layout, single pass.
// ---------------------------------------------------------------------------
__global__ __launch_bounds__(256)
void head_kernel(const float* __restrict__ b_f0, const float* __restrict__ b_en,
                 float* __restrict__ out) {
    __shared__ float sh[8][4][32];
    int tid = threadIdx.x;
    int tt = tid & 31, oct = tid >> 5;
    int rowBase = blockIdx.x * 32;
    int b = rowBase >> 11, t0 = rowBase & (Tt - 1);

    const float* hp = g_ht + ((size_t)(b * Dd) + oct * 64) * Tt + t0 + tt;
    const float* swf = g_swf0 + oct * 64;
    const float* swe = g_swen + oct * 64;

    float s1 = 0.0f, s2 = 0.0f, sf = 0.0f, se = 0.0f;
#pragma unroll 8
    for (int dd = 0; dd < 64; dd++) {
        float v = hp[(size_t)dd * Tt];
        s1 += v;
        s2 = fmaf(v, v, s2);
        sf = fmaf(v, __ldg(swf + dd), sf);
        se = fmaf(v, __ldg(swe + dd), se);
    }
    sh[oct][0][tt] = s1; sh[oct][1][tt] = s2;
    sh[oct][2][tt] = sf; sh[oct][3][tt] = se;
    __syncthreads();

    if (tid < 32) {
        float a0 = 0.0f, a1 = 0.0f, a2 = 0.0f, a3 = 0.0f;
#pragma unroll
        for (int o = 0; o < 8; o++) {
            a0 += sh[o][0][tt]; a1 += sh[o][1][tt];
            a2 += sh[o][2][tt]; a3 += sh[o][3][tt];
        }
        float mu = a0 * (1.0f / Dd);
        float var = a1 * (1.0f / Dd) - mu * mu;
        float rstd = rsqrtf(var + 1e-5f);
        out[rowBase + tt]                   = rstd * (a2 - mu * g_hc[0]) + g_hc[1] + b_f0[0];
        out[(size_t)Bb * Tt + rowBase + tt] = rstd * (a3 - mu * g_hc[2]) + g_hc[3] + b_en[0];
    }
}

// ---------------------------------------------------------------------------
extern "C" void kernel_launch(void* const* d_in, const int* in_sizes, int n_in,
                              void* d_out, int out_size) {
    const float* text_emb = (const float*)d_in[0];
    const float* W_in     = (const float*)d_in[1];
    const float* b_in     = (const float*)d_in[2];
    const float* freq_pe  = (const float*)d_in[3];
    const float* A_log    = (const float*)d_in[4];
    const float* B_ssm    = (const float*)d_in[5];
    const float* C_ssm    = (const float*)d_in[6];
    const float* log_dt   = (const float*)d_in[7];
    const float* D_skip   = (const float*)d_in[8];
    const float* ln_f0_s  = (const float*)d_in[9];
    const float* ln_f0_b  = (const float*)d_in[10];
    const float* W_f0     = (const float*)d_in[11];
    const float* b_f0     = (const float*)d_in[12];
    const float* ln_en_s  = (const float*)d_in[13];
    const float* ln_en_b  = (const float*)d_in[14];
    const float* W_en     = (const float*)d_in[15];
    const float* b_en     = (const float*)d_in[16];
    float* out = (float*)d_out;

    precompute_kernel<<<(Ll * DN + 255) / 256, 256>>>(A_log, B_ssm, C_ssm, log_dt);
    head_prep_kernel<<<1, Dd>>>(ln_f0_s, ln_f0_b, W_f0, ln_en_s, ln_en_b, W_en);

    dim3 ggrid(Dd / 64, (Bb * Tt) / 128);
    gemm_tf32_kernel<<<ggrid, 256>>>(text_emb, W_in, b_in, freq_pe);

    s4_stack_kernel<<<Bb * (Dd / DBLK), 128>>>(D_skip);

    head_kernel<<<(Bb * Tt) / 32, 256>>>(b_f0, b_en, out);
}